// round 13
// baseline (speedup 1.0000x reference)
#include <cuda_runtime.h>
#include <cuda_bf16.h>
#include <math.h>
#include <stdint.h>

// ---------------- problem constants ----------------
#define VSZ   128
#define V1SZ  129
#define HSZ   512
#define H4SZ  2048
#define ESZ   128
#define NEXN  4
#define LLEN  32
#define BSZ   512
#define TLEN  32
#define NB    (NEXN * BSZ)      // 2048
#define NT_ALL (TLEN * NB)      // 65536
#define NEGV  (-1e9f)
#define NBH   ((size_t)NB * HSZ)

// ---------------- device scratch (allocation-free) ----------------
__device__ __nv_bfloat16 g_Hs[(size_t)LLEN * NB * HSZ];
__device__ __nv_bfloat16 g_Hd[(size_t)TLEN * NB * HSZ];
__device__ __nv_bfloat16 g_hbf[NB * HSZ];
__device__ __nv_bfloat16 g_ubf[(size_t)NT_ALL * HSZ];
__device__ __nv_bfloat16 g_hcbf[(size_t)NT_ALL * 2 * HSZ];
__device__ float g_fc[(size_t)NT_ALL * ESZ];
__device__ float g_mask[NEXN * LLEN * BSZ];
__device__ int   g_idx[NB];
__device__ unsigned int g_bar;
__device__ __nv_bfloat16 g_WhhPE[H4SZ * HSZ];
__device__ __nv_bfloat16 g_WhhPD[H4SZ * HSZ];
__device__ float g_WihTE[V1SZ * H4SZ];
__device__ float g_WihTD[V1SZ * H4SZ];
__device__ __nv_bfloat16 g_Awb[HSZ * HSZ];
__device__ __nv_bfloat16 g_Wwb[ESZ * 2 * HSZ];

__device__ __forceinline__ float sigmoidf_(float x) { return 1.f / (1.f + expf(-x)); }

// ---------------- ptx helpers ----------------
__device__ __forceinline__ void cp_async16(uint32_t dst, const void* src) {
    asm volatile("cp.async.cg.shared.global [%0], [%1], 16;\n" :: "r"(dst), "l"(src));
}
__device__ __forceinline__ void cp_commit() { asm volatile("cp.async.commit_group;\n"); }
template<int N> __device__ __forceinline__ void cp_wait() {
    asm volatile("cp.async.wait_group %0;\n" :: "n"(N));
}
__device__ __forceinline__ void ldm_x4(uint32_t& r0, uint32_t& r1, uint32_t& r2, uint32_t& r3,
                                       uint32_t addr) {
    asm volatile("ldmatrix.sync.aligned.m8n8.x4.shared.b16 {%0,%1,%2,%3}, [%4];"
                 : "=r"(r0), "=r"(r1), "=r"(r2), "=r"(r3) : "r"(addr));
}

// ---------------- prep kernels ----------------
__global__ void permute_whh_kernel(const float* __restrict__ Whh,
                                   __nv_bfloat16* __restrict__ WhhP) {
    int np = blockIdx.x;
    int h = np >> 2, g = np & 3;
    int orig = g * HSZ + h;
    for (int k = threadIdx.x; k < HSZ; k += 256)
        WhhP[np * HSZ + k] = __float2bfloat16_rn(Whh[(size_t)orig * HSZ + k]);
}

__global__ void transpose_wih_both_kernel(
    const float* __restrict__ WihE, const float* __restrict__ bihE, const float* __restrict__ bhhE,
    const float* __restrict__ WihD, const float* __restrict__ bihD, const float* __restrict__ bhhD) {
    int v = blockIdx.x;
    const float* Wih = blockIdx.y ? WihD : WihE;
    const float* bih = blockIdx.y ? bihD : bihE;
    const float* bhh = blockIdx.y ? bhhD : bhhE;
    float* WihT = blockIdx.y ? g_WihTD : g_WihTE;
    for (int np = threadIdx.x; np < H4SZ; np += 256) {
        int h = np >> 2, g = np & 3;
        int orig = g * HSZ + h;
        WihT[(size_t)v * H4SZ + np] = Wih[(size_t)orig * V1SZ + v] + bih[orig] + bhh[orig];
    }
}

__global__ void convert_both_kernel(const float* __restrict__ Aw, const float* __restrict__ Ww) {
    int i = blockIdx.x * blockDim.x + threadIdx.x;
    if (i < HSZ * HSZ) g_Awb[i] = __float2bfloat16_rn(Aw[i]);
    if (i < ESZ * 2 * HSZ) g_Wwb[i] = __float2bfloat16_rn(Ww[i]);
}

__global__ void init_all_kernel(const float* __restrict__ h0, const int* __restrict__ inputs) {
    int idx = blockIdx.x * blockDim.x + threadIdx.x;
    if (idx == 0) g_bar = 0u;
    if (idx < NB * HSZ) g_hbf[idx] = __float2bfloat16_rn(h0[idx & (HSZ - 1)]);
    if (idx < NB) {
        int r = idx;
        int j = r / BSZ, b = r % BSZ;
        float a = 1.f;
        int cnt = 0;
        #pragma unroll
        for (int l = 0; l < LLEN; l++) {
            g_mask[(j * LLEN + l) * BSZ + b] = (a > 0.f) ? 0.f : NEGV;
            cnt += (a > 0.f) ? 1 : 0;
            a *= (inputs[(j * LLEN + l) * BSZ + b] != VSZ) ? 1.f : 0.f;
        }
        g_idx[r] = cnt - 1;
    }
}

// ================= persistent fused LSTM chain, Whh resident in SMEM =================
// 128 CTAs (16 n-tiles x 8 m-tiles), CTA tile 256x128, 512 threads (16 warps 8x2,
// warp tile 32x64). B (Whh slab, 128KB) loaded ONCE per phase into SMEM; A streams
// through a 2-stage cp.async pipeline. c tile in SMEM. Grid barrier between steps.
__global__ __launch_bounds__(512, 1)
void chain_kernel(const int* __restrict__ inputs, const int* __restrict__ target,
                  const float* __restrict__ enc_c0, const float* __restrict__ dec_c0) {
    constexpr int BM = 256, BN = 128, BK = 32, K = HSZ;
    constexpr int AST = 40;                        // A row stride (80B), conflict-free
    constexpr int BST = 520;                       // B row stride (1040B): rows step 16B in banks
    constexpr int MT = 2, NTc = 8;
    constexpr int ASTAGE = BM * AST;               // 10240 bf16 per A stage
    constexpr int NIT = K / BK;                    // 16
    constexpr int NCTA = 128;

    extern __shared__ __nv_bfloat16 smd[];
    __nv_bfloat16* bres = smd + 2 * ASTAGE;                      // B resident: 128x520
    float* c_s = (float*)(bres + BN * BST);                      // [32 h][256 rows]
    const uint32_t smbase = (uint32_t)__cvta_generic_to_shared(smd);
    const uint32_t bresbase = (uint32_t)__cvta_generic_to_shared(bres);

    const int tid = threadIdx.x;
    const int warp = tid >> 5, lane = tid & 31;
    const int wm = warp >> 1;
    const int wn = warp & 1;
    const int m0 = blockIdx.y * BM, n0 = blockIdx.x * BN;
    const unsigned FULL = 0xffffffffu;

    for (int i = tid; i < 32 * 256; i += 512)
        c_s[i] = enc_c0[blockIdx.x * 32 + (i >> 8)];

    // load encoder B slab (once)
    {
        const __nv_bfloat16* Bw = g_WhhPE;
        #pragma unroll
        for (int ii = 0; ii < 16; ii++) {
            int c = tid + ii * 512;               // 8192 chunks of 8 bf16
            int row = c >> 6, part = c & 63;
            cp_async16(bresbase + (uint32_t)((row * BST + part * 8) * 2),
                       Bw + (size_t)(n0 + row) * K + part * 8);
        }
        cp_commit();
        cp_wait<0>();
    }
    __syncthreads();

    for (int t = 0; t < LLEN + TLEN; t++) {
        const bool enc = t < LLEN;
        const float* WihT = enc ? g_WihTE : g_WihTD;
        const __nv_bfloat16* A;
        int gather = 0;
        if (t == 0)            A = g_hbf;
        else if (t < LLEN)     A = g_Hs + (size_t)(t - 1) * NBH;
        else if (t == LLEN)  { A = g_Hs; gather = 1; }
        else                   A = g_Hd + (size_t)(t - LLEN - 1) * NBH;
        __nv_bfloat16* Hout = enc ? (g_Hs + (size_t)t * NBH)
                                  : (g_Hd + (size_t)(t - LLEN) * NBH);
        int tokmode; const int* tokp = nullptr;
        if (t < LLEN)      { tokmode = 1; tokp = inputs + t * BSZ; }
        else if (t == LLEN)  tokmode = 0;
        else               { tokmode = 2; tokp = target + (t - LLEN - 1) * BSZ; }

        if (t == LLEN) {      // decoder phase: reload B slab + reset c
            __syncthreads();
            const __nv_bfloat16* Bw = g_WhhPD;
            #pragma unroll
            for (int ii = 0; ii < 16; ii++) {
                int c = tid + ii * 512;
                int row = c >> 6, part = c & 63;
                cp_async16(bresbase + (uint32_t)((row * BST + part * 8) * 2),
                           Bw + (size_t)(n0 + row) * K + part * 8);
            }
            cp_commit();
            for (int i = tid; i < 32 * 256; i += 512)
                c_s[i] = dec_c0[blockIdx.x * 32 + (i >> 8)];
            cp_wait<0>();
            __syncthreads();
        }

        float acc[MT][NTc][4];
        #pragma unroll
        for (int mt = 0; mt < MT; mt++)
            #pragma unroll
            for (int nt = 0; nt < NTc; nt++)
                #pragma unroll
                for (int q = 0; q < 4; q++) acc[mt][nt][q] = 0.f;

        auto load_stage = [&](int it) {
            const int k0 = it * BK;
            const uint32_t base = smbase + (uint32_t)(it & 1) * ASTAGE * 2;
            #pragma unroll
            for (int ii = 0; ii < BM * 4 / 512; ii++) {
                int c = tid + ii * 512;
                int row = c >> 2, part = c & 3;
                const __nv_bfloat16* src;
                if (gather) {
                    int rg2 = m0 + row;
                    src = g_Hs + ((size_t)g_idx[rg2] * NB + rg2) * HSZ + k0 + part * 8;
                } else {
                    src = A + (size_t)(m0 + row) * K + k0 + part * 8;
                }
                cp_async16(base + (uint32_t)((row * AST + part * 8) * 2), src);
            }
            cp_commit();
        };

        load_stage(0);

        for (int it = 0; it < NIT; it++) {
            if (it + 1 < NIT) { load_stage(it + 1); cp_wait<1>(); }
            else              { cp_wait<0>(); }
            __syncthreads();

            const uint32_t aBase = smbase + (uint32_t)(it & 1) * ASTAGE * 2;

            #pragma unroll
            for (int kk = 0; kk < 2; kk++) {
                uint32_t a[MT][4];
                #pragma unroll
                for (int mt = 0; mt < MT; mt++) {
                    int row = wm * 32 + mt * 16 + (lane & 15);
                    int col = kk * 16 + (lane >> 4) * 8;
                    ldm_x4(a[mt][0], a[mt][1], a[mt][2], a[mt][3],
                           aBase + (uint32_t)((row * AST + col) * 2));
                }
                uint32_t b[NTc][2];
                #pragma unroll
                for (int ntp = 0; ntp < NTc / 2; ntp++) {
                    int row = wn * 64 + ntp * 16 + ((lane >> 4) << 3) + (lane & 7);
                    int col = it * BK + kk * 16 + ((lane >> 3) & 1) * 8;
                    ldm_x4(b[2 * ntp][0], b[2 * ntp][1], b[2 * ntp + 1][0], b[2 * ntp + 1][1],
                           bresbase + (uint32_t)((row * BST + col) * 2));
                }
                #pragma unroll
                for (int mt = 0; mt < MT; mt++)
                    #pragma unroll
                    for (int nt = 0; nt < NTc; nt++) {
                        asm volatile(
                            "mma.sync.aligned.m16n8k16.row.col.f32.bf16.bf16.f32 "
                            "{%0,%1,%2,%3}, {%4,%5,%6,%7}, {%8,%9}, {%0,%1,%2,%3};"
                            : "+f"(acc[mt][nt][0]), "+f"(acc[mt][nt][1]),
                              "+f"(acc[mt][nt][2]), "+f"(acc[mt][nt][3])
                            : "r"(a[mt][0]), "r"(a[mt][1]), "r"(a[mt][2]), "r"(a[mt][3]),
                              "r"(b[nt][0]), "r"(b[nt][1]));
                    }
            }
            __syncthreads();
        }

        // -------- fused LSTM epilogue --------
        #pragma unroll
        for (int mt = 0; mt < MT; mt++) {
            int rl_lo = wm * 32 + mt * 16 + (lane >> 2);
            int rl_hi = rl_lo + 8;
            int r_lo = m0 + rl_lo, r_hi = m0 + rl_hi;
            int tok_lo = VSZ, tok_hi = VSZ;
            if (tokmode == 1) {
                tok_lo = tokp[(r_lo / BSZ) * (LLEN * BSZ) + (r_lo % BSZ)];
                tok_hi = tokp[(r_hi / BSZ) * (LLEN * BSZ) + (r_hi % BSZ)];
            } else if (tokmode == 2) {
                tok_lo = tokp[r_lo % BSZ];
                tok_hi = tokp[r_hi % BSZ];
            }
            const float* wl = WihT + (size_t)tok_lo * H4SZ;
            const float* wh_ = WihT + (size_t)tok_hi * H4SZ;
            #pragma unroll
            for (int nt = 0; nt < NTc; nt++) {
                int c0 = n0 + wn * 64 + nt * 8 + 2 * (lane & 3);
                float2 el = *(const float2*)&wl[c0];
                float2 eh = *(const float2*)&wh_[c0];
                float v00 = acc[mt][nt][0] + el.x;
                float v01 = acc[mt][nt][1] + el.y;
                float v10 = acc[mt][nt][2] + eh.x;
                float v11 = acc[mt][nt][3] + eh.y;
                float p00 = __shfl_xor_sync(FULL, v00, 1);
                float p01 = __shfl_xor_sync(FULL, v01, 1);
                float p10 = __shfl_xor_sync(FULL, v10, 1);
                float p11 = __shfl_xor_sync(FULL, v11, 1);
                if ((lane & 1) == 0) {
                    int hl = wn * 16 + nt * 2 + ((lane & 3) >> 1);
                    int hg = blockIdx.x * 32 + hl;
                    {
                        float cold = c_s[hl * 256 + rl_lo];
                        float c2 = sigmoidf_(v01) * cold + sigmoidf_(v00) * tanhf(p00);
                        float h2 = sigmoidf_(p01) * tanhf(c2);
                        c_s[hl * 256 + rl_lo] = c2;
                        Hout[(size_t)r_lo * HSZ + hg] = __float2bfloat16_rn(h2);
                    }
                    {
                        float cold = c_s[hl * 256 + rl_hi];
                        float c2 = sigmoidf_(v11) * cold + sigmoidf_(v10) * tanhf(p10);
                        float h2 = sigmoidf_(p11) * tanhf(c2);
                        c_s[hl * 256 + rl_hi] = c2;
                        Hout[(size_t)r_hi * HSZ + hg] = __float2bfloat16_rn(h2);
                    }
                }
            }
        }

        // -------- grid barrier --------
        __threadfence();
        __syncthreads();
        if (tid == 0) {
            atomicAdd(&g_bar, 1u);
            unsigned need = (unsigned)NCTA * (unsigned)(t + 1);
            while (*(volatile unsigned*)&g_bar < need) { }
        }
        __syncthreads();
        __threadfence();
    }
}

// ================= generic bf16 GEMM (batched tail) =================
// MODE 2: tanh(+b1) f32 store; MODE 4: bf16 store
template<int MODE>
__global__ __launch_bounds__(256)
void bf16_gemm_kernel(const __nv_bfloat16* __restrict__ A, const __nv_bfloat16* __restrict__ Bw,
                      void* __restrict__ Cv, int M, int N, int K,
                      const float* __restrict__ b1) {
    constexpr int BM = 128, BN = 128, BK = 32;
    constexpr int AST = 40;
    constexpr int MT = 2, NTc = 8;
    constexpr int STAGE = (BM + BN) * AST;

    __shared__ __nv_bfloat16 sm[2 * STAGE];
    const uint32_t smbase = (uint32_t)__cvta_generic_to_shared(sm);

    const int tid = threadIdx.x;
    const int warp = tid >> 5, lane = tid & 31;
    const int wm = warp >> 1;
    const int wn = warp & 1;
    const int m0 = blockIdx.y * BM, n0 = blockIdx.x * BN;
    const int NIT = K / BK;

    float acc[MT][NTc][4];
    #pragma unroll
    for (int mt = 0; mt < MT; mt++)
        #pragma unroll
        for (int nt = 0; nt < NTc; nt++)
            #pragma unroll
            for (int q = 0; q < 4; q++) acc[mt][nt][q] = 0.f;

    auto load_stage = [&](int it, int buf) {
        const int k0 = it * BK;
        const uint32_t base = smbase + (uint32_t)buf * STAGE * 2;
        #pragma unroll
        for (int c = tid; c < (BM + BN) * 4; c += 256) {
            bool isB = c >= BM * 4;
            int cc = isB ? c - BM * 4 : c;
            int row = cc >> 2, part = cc & 3;
            const __nv_bfloat16* src = isB
                ? (Bw + (size_t)(n0 + row) * K + k0 + part * 8)
                : (A  + (size_t)(m0 + row) * K + k0 + part * 8);
            uint32_t dst = base + (uint32_t)(((isB ? BM + row : row) * AST + part * 8) * 2);
            cp_async16(dst, src);
        }
    };

    load_stage(0, 0);
    cp_commit();

    for (int it = 0; it < NIT; it++) {
        if (it + 1 < NIT) { load_stage(it + 1, (it + 1) & 1); cp_commit(); cp_wait<1>(); }
        else              { cp_wait<0>(); }
        __syncthreads();

        const uint32_t aBase = smbase + (uint32_t)(it & 1) * STAGE * 2;
        const uint32_t bBase = aBase + BM * AST * 2;

        #pragma unroll
        for (int kk = 0; kk < 2; kk++) {
            uint32_t a[MT][4];
            #pragma unroll
            for (int mt = 0; mt < MT; mt++) {
                int row = wm * 32 + mt * 16 + (lane & 15);
                int col = kk * 16 + (lane >> 4) * 8;
                ldm_x4(a[mt][0], a[mt][1], a[mt][2], a[mt][3],
                       aBase + (uint32_t)((row * AST + col) * 2));
            }
            uint32_t b[NTc][2];
            #pragma unroll
            for (int ntp = 0; ntp < NTc / 2; ntp++) {
                int row = wn * 64 + ntp * 16 + ((lane >> 4) << 3) + (lane & 7);
                int col = kk * 16 + ((lane >> 3) & 1) * 8;
                ldm_x4(b[2 * ntp][0], b[2 * ntp][1], b[2 * ntp + 1][0], b[2 * ntp + 1][1],
                       bBase + (uint32_t)((row * AST + col) * 2));
            }
            #pragma unroll
            for (int mt = 0; mt < MT; mt++)
                #pragma unroll
                for (int nt = 0; nt < NTc; nt++) {
                    asm volatile(
                        "mma.sync.aligned.m16n8k16.row.col.f32.bf16.bf16.f32 "
                        "{%0,%1,%2,%3}, {%4,%5,%6,%7}, {%8,%9}, {%0,%1,%2,%3};"
                        : "+f"(acc[mt][nt][0]), "+f"(acc[mt][nt][1]),
                          "+f"(acc[mt][nt][2]), "+f"(acc[mt][nt][3])
                        : "r"(a[mt][0]), "r"(a[mt][1]), "r"(a[mt][2]), "r"(a[mt][3]),
                          "r"(b[nt][0]), "r"(b[nt][1]));
                }
        }
        __syncthreads();
    }

    float* Cf = (float*)Cv;
    __nv_bfloat16* Cb = (__nv_bfloat16*)Cv;
    #pragma unroll
    for (int mt = 0; mt < MT; mt++) {
        int r_lo = m0 + wm * 32 + mt * 16 + (lane >> 2);
        int r_hi = r_lo + 8;
        #pragma unroll
        for (int nt = 0; nt < NTc; nt++) {
            int c0 = n0 + wn * 64 + nt * 8 + 2 * (lane & 3);
            float v00 = acc[mt][nt][0], v01 = acc[mt][nt][1];
            float v10 = acc[mt][nt][2], v11 = acc[mt][nt][3];
            if (MODE == 2) {
                float bb0 = b1[c0], bb1 = b1[c0 + 1];
                v00 = tanhf(v00 + bb0); v01 = tanhf(v01 + bb1);
                v10 = tanhf(v10 + bb0); v11 = tanhf(v11 + bb1);
            }
            if (MODE == 4) {
                __nv_bfloat162 lo = __floats2bfloat162_rn(v00, v01);
                __nv_bfloat162 hi = __floats2bfloat162_rn(v10, v11);
                *(__nv_bfloat162*)&Cb[(size_t)r_lo * N + c0] = lo;
                *(__nv_bfloat162*)&Cb[(size_t)r_hi * N + c0] = hi;
            } else {
                Cf[(size_t)r_lo * N + c0] = v00;
                Cf[(size_t)r_lo * N + c0 + 1] = v01;
                Cf[(size_t)r_hi * N + c0] = v10;
                Cf[(size_t)r_hi * N + c0 + 1] = v11;
            }
        }
    }
}

// ---------------- batched attention over all 32 timesteps ----------------
__global__ __launch_bounds__(256) void attn_all_kernel() {
    __shared__ __nv_bfloat16 hs_s[LLEN * HSZ];
    __shared__ float u_s[HSZ];
    __shared__ float sc[LLEN];
    __shared__ float mask_s[LLEN];

    const int r = blockIdx.x;
    const int j = r / BSZ;
    const int tid = threadIdx.x;
    const int warp = tid >> 5, lane = tid & 31;

    #pragma unroll
    for (int idx = tid; idx < LLEN * HSZ / 8; idx += 256) {
        int l = idx >> 6;
        int c8 = (idx & 63) * 8;
        uint4 v = *(const uint4*)&g_Hs[((size_t)l * NB + r) * HSZ + c8];
        *(uint4*)&hs_s[l * HSZ + c8] = v;
    }
    if (tid < LLEN) mask_s[tid] = g_mask[(j * LLEN + tid) * BSZ + (r % BSZ)];
    __syncthreads();

    for (int t = 0; t < TLEN; t++) {
        const size_t row = (size_t)t * NB + r;
        for (int k = tid; k < HSZ; k += 256)
            u_s[k] = __bfloat162float(g_ubf[row * HSZ + k]);
        __syncthreads();

        for (int l = warp; l < LLEN; l += 8) {
            float s = 0.f;
            for (int k = lane; k < HSZ; k += 32)
                s += __bfloat162float(hs_s[l * HSZ + k]) * u_s[k];
            #pragma unroll
            for (int off = 16; off > 0; off >>= 1) s += __shfl_down_sync(0xffffffffu, s, off);
            if (lane == 0) sc[l] = s + mask_s[l];
        }
        __syncthreads();

        if (warp == 0) {
            float v = sc[lane];
            float mx = v;
            #pragma unroll
            for (int off = 16; off > 0; off >>= 1) mx = fmaxf(mx, __shfl_xor_sync(0xffffffffu, mx, off));
            float e = expf(v - mx);
            float ssum = e;
            #pragma unroll
            for (int off = 16; off > 0; off >>= 1) ssum += __shfl_xor_sync(0xffffffffu, ssum, off);
            sc[lane] = e / ssum;
        }
        __syncthreads();

        __nv_bfloat16* hc = g_hcbf + row * (2 * HSZ);
        #pragma unroll
        for (int kq = 0; kq < 2; kq++) {
            int k = tid + kq * 256;
            float cx = 0.f;
            #pragma unroll
            for (int l = 0; l < LLEN; l++) cx += sc[l] * __bfloat162float(hs_s[l * HSZ + k]);
            hc[HSZ + k] = __float2bfloat16_rn(cx);
        }
        if (tid < 64) {
            uint4 v = *(const uint4*)&g_Hd[row * HSZ + tid * 8];
            *(uint4*)&hc[tid * 8] = v;
        }
        __syncthreads();
    }
}

// ---------------- pool + logits + log-softmax + score over all t ----------------
__global__ __launch_bounds__(256) void pool_score_all_kernel(
    const float* __restrict__ Vw, const float* __restrict__ Vb,
    const int* __restrict__ target, float* __restrict__ out) {
    extern __shared__ float dsm[];
    float* Vw_s = dsm;
    float* m_s  = dsm + ESZ * 132;
    float* lgs  = m_s + ESZ;
    __shared__ float red[2];

    const int b = blockIdx.x;
    const int tid = threadIdx.x;
    const int lane = tid & 31;

    for (int idx = tid; idx < V1SZ * ESZ; idx += 256) {
        int v = idx >> 7, e = idx & 127;
        Vw_s[e * 132 + v] = Vw[(size_t)v * ESZ + e];
    }
    __syncthreads();

    float score = 0.f, act = 1.f;
    for (int t = 0; t < TLEN; t++) {
        if (tid < ESZ) {
            const size_t base = ((size_t)t * NB + b) * ESZ + tid;
            float m = g_fc[base];
            #pragma unroll
            for (int jj = 1; jj < NEXN; jj++)
                m = fmaxf(m, g_fc[base + (size_t)jj * BSZ * ESZ]);
            m_s[tid] = m;
        }
        __syncthreads();

        if (tid < V1SZ) {
            float s = Vb[tid];
            #pragma unroll 8
            for (int e = 0; e < ESZ; e++) s += m_s[e] * Vw_s[e * 132 + tid];
            lgs[tid] = s;
        }
        __syncthreads();

        if (tid < 32) {
            float mx = -1e30f;
            for (int v = lane; v < V1SZ; v += 32) mx = fmaxf(mx, lgs[v]);
            #pragma unroll
            for (int off = 16; off > 0; off >>= 1) mx = fmaxf(mx, __shfl_xor_sync(0xffffffffu, mx, off));
            float ssum = 0.f;
            for (int v = lane; v < V1SZ; v += 32) ssum += expf(lgs[v] - mx);
            #pragma unroll
            for (int off = 16; off > 0; off >>= 1) ssum += __shfl_xor_sync(0xffffffffu, ssum, off);
            if (lane == 0) { red[0] = mx; red[1] = ssum; }
        }
        __syncthreads();

        int tg = target[t * BSZ + b];
        float ls = lgs[tg] - red[0] - logf(red[1]);
        score += ls * act;
        act *= (tg != VSZ) ? 1.f : 0.f;
        __syncthreads();
    }
    if (tid == 0) out[b] = score;
}

// ---------------- host orchestration ----------------
extern "C" void kernel_launch(void* const* d_in, const int* in_sizes, int n_in,
                              void* d_out, int out_size) {
    const int*   inputs  = (const int*)  d_in[0];
    const int*   target  = (const int*)  d_in[1];
    const float* enc_Wih = (const float*)d_in[2];
    const float* enc_Whh = (const float*)d_in[3];
    const float* enc_bih = (const float*)d_in[4];
    const float* enc_bhh = (const float*)d_in[5];
    const float* enc_h0  = (const float*)d_in[6];
    const float* enc_c0  = (const float*)d_in[7];
    const float* dec_Wih = (const float*)d_in[8];
    const float* dec_Whh = (const float*)d_in[9];
    const float* dec_bih = (const float*)d_in[10];
    const float* dec_bhh = (const float*)d_in[11];
    const float* dec_c0  = (const float*)d_in[12];
    const float* W_w     = (const float*)d_in[13];
    const float* W_b     = (const float*)d_in[14];
    const float* V_w     = (const float*)d_in[15];
    const float* V_b     = (const float*)d_in[16];
    const float* A_w     = (const float*)d_in[17];
    float* out = (float*)d_out;

    __nv_bfloat16 *WhhPE_p, *WhhPD_p, *Awb_p, *Wwb_p, *hcbf_p, *Hd_p, *ubf_p;
    float *fc_p;
    cudaGetSymbolAddress((void**)&WhhPE_p, g_WhhPE);
    cudaGetSymbolAddress((void**)&WhhPD_p, g_WhhPD);
    cudaGetSymbolAddress((void**)&Awb_p, g_Awb);
    cudaGetSymbolAddress((void**)&Wwb_p, g_Wwb);
    cudaGetSymbolAddress((void**)&hcbf_p, g_hcbf);
    cudaGetSymbolAddress((void**)&Hd_p, g_Hd);
    cudaGetSymbolAddress((void**)&ubf_p, g_ubf);
    cudaGetSymbolAddress((void**)&fc_p, g_fc);

    const int ps_smem = (ESZ * 132 + ESZ + 132) * (int)sizeof(float);
    cudaFuncSetAttribute(pool_score_all_kernel, cudaFuncAttributeMaxDynamicSharedMemorySize, ps_smem);
    // 2 A stages (2*10240*2) + B resident (128*520*2) + c (32*256*4) = 40960+133120+32768 = 206848 B
    const int chain_smem = 2 * 256 * 40 * 2 + 128 * 520 * 2 + 32 * 256 * 4;
    cudaFuncSetAttribute(chain_kernel, cudaFuncAttributeMaxDynamicSharedMemorySize, chain_smem);

    // ---- prep ----
    permute_whh_kernel<<<H4SZ, 256>>>(enc_Whh, WhhPE_p);
    permute_whh_kernel<<<H4SZ, 256>>>(dec_Whh, WhhPD_p);
    transpose_wih_both_kernel<<<dim3(V1SZ, 2), 256>>>(enc_Wih, enc_bih, enc_bhh,
                                                      dec_Wih, dec_bih, dec_bhh);
    convert_both_kernel<<<(HSZ * HSZ + 255) / 256, 256>>>(A_w, W_w);
    init_all_kernel<<<(NB * HSZ + 255) / 256, 256>>>(enc_h0, inputs);

    // ---- persistent LSTM chain ----
    chain_kernel<<<dim3(H4SZ / 128, NB / 256), 512, chain_smem>>>(
        inputs, target, enc_c0, dec_c0);

    // ---- batched decoder tail ----
    bf16_gemm_kernel<4><<<dim3(HSZ / 128, NT_ALL / 128), 256>>>(
        Hd_p, Awb_p, (void*)ubf_p, NT_ALL, HSZ, HSZ, nullptr);
    attn_all_kernel<<<NB, 256>>>();
    bf16_gemm_kernel<2><<<dim3(ESZ / 128, NT_ALL / 128), 256>>>(
        hcbf_p, Wwb_p, (void*)fc_p, NT_ALL, ESZ, 2 * HSZ, W_b);
    pool_score_all_kernel<<<BSZ, 256, ps_smem>>>(V_w, V_b, target, out);
}

// round 15
// speedup vs baseline: 1.0038x; 1.0038x over previous
#include <cuda_runtime.h>
#include <cuda_bf16.h>
#include <math.h>
#include <stdint.h>

// ---------------- problem constants ----------------
#define VSZ   128
#define V1SZ  129
#define HSZ   512
#define H4SZ  2048
#define ESZ   128
#define NEXN  4
#define LLEN  32
#define BSZ   512
#define TLEN  32
#define NB    (NEXN * BSZ)      // 2048
#define NT_ALL (TLEN * NB)      // 65536
#define NEGV  (-1e9f)
#define NBH   ((size_t)NB * HSZ)

// ---------------- device scratch (allocation-free) ----------------
__device__ __nv_bfloat16 g_Hs[(size_t)LLEN * NB * HSZ];
__device__ __nv_bfloat16 g_Hd[(size_t)TLEN * NB * HSZ];
__device__ __nv_bfloat16 g_hbf[NB * HSZ];
__device__ __nv_bfloat16 g_ubf[(size_t)NT_ALL * HSZ];
__device__ __nv_bfloat16 g_hcbf[(size_t)NT_ALL * 2 * HSZ];
__device__ float g_fc[(size_t)NT_ALL * ESZ];
__device__ float g_mask[NEXN * LLEN * BSZ];
__device__ int   g_idx[NB];
__device__ unsigned int g_bars[8];                 // per-m-tile sub-barriers
__device__ __nv_bfloat16 g_WhhPE[H4SZ * HSZ];
__device__ __nv_bfloat16 g_WhhPD[H4SZ * HSZ];
__device__ float g_WihTE[V1SZ * H4SZ];
__device__ float g_WihTD[V1SZ * H4SZ];
__device__ __nv_bfloat16 g_Awb[HSZ * HSZ];
__device__ __nv_bfloat16 g_Wwb[ESZ * 2 * HSZ];

__device__ __forceinline__ float sigmoidf_(float x) { return 1.f / (1.f + expf(-x)); }

// ---------------- ptx helpers ----------------
__device__ __forceinline__ void cp_async16(uint32_t dst, const void* src) {
    asm volatile("cp.async.cg.shared.global [%0], [%1], 16;\n" :: "r"(dst), "l"(src));
}
__device__ __forceinline__ void cp_commit() { asm volatile("cp.async.commit_group;\n"); }
template<int N> __device__ __forceinline__ void cp_wait() {
    asm volatile("cp.async.wait_group %0;\n" :: "n"(N));
}
__device__ __forceinline__ void ldm_x4(uint32_t& r0, uint32_t& r1, uint32_t& r2, uint32_t& r3,
                                       uint32_t addr) {
    asm volatile("ldmatrix.sync.aligned.m8n8.x4.shared.b16 {%0,%1,%2,%3}, [%4];"
                 : "=r"(r0), "=r"(r1), "=r"(r2), "=r"(r3) : "r"(addr));
}

// ---------------- prep kernels ----------------
__global__ void permute_whh_kernel(const float* __restrict__ Whh,
                                   __nv_bfloat16* __restrict__ WhhP) {
    int np = blockIdx.x;
    int h = np >> 2, g = np & 3;
    int orig = g * HSZ + h;
    for (int k = threadIdx.x; k < HSZ; k += 256)
        WhhP[np * HSZ + k] = __float2bfloat16_rn(Whh[(size_t)orig * HSZ + k]);
}

__global__ void transpose_wih_both_kernel(
    const float* __restrict__ WihE, const float* __restrict__ bihE, const float* __restrict__ bhhE,
    const float* __restrict__ WihD, const float* __restrict__ bihD, const float* __restrict__ bhhD) {
    int v = blockIdx.x;
    const float* Wih = blockIdx.y ? WihD : WihE;
    const float* bih = blockIdx.y ? bihD : bihE;
    const float* bhh = blockIdx.y ? bhhD : bhhE;
    float* WihT = blockIdx.y ? g_WihTD : g_WihTE;
    for (int np = threadIdx.x; np < H4SZ; np += 256) {
        int h = np >> 2, g = np & 3;
        int orig = g * HSZ + h;
        WihT[(size_t)v * H4SZ + np] = Wih[(size_t)orig * V1SZ + v] + bih[orig] + bhh[orig];
    }
}

__global__ void convert_both_kernel(const float* __restrict__ Aw, const float* __restrict__ Ww) {
    int i = blockIdx.x * blockDim.x + threadIdx.x;
    if (i < HSZ * HSZ) g_Awb[i] = __float2bfloat16_rn(Aw[i]);
    if (i < ESZ * 2 * HSZ) g_Wwb[i] = __float2bfloat16_rn(Ww[i]);
}

__global__ void init_all_kernel(const float* __restrict__ h0, const int* __restrict__ inputs) {
    int idx = blockIdx.x * blockDim.x + threadIdx.x;
    if (idx < 8) g_bars[idx] = 0u;
    if (idx < NB * HSZ) g_hbf[idx] = __float2bfloat16_rn(h0[idx & (HSZ - 1)]);
    if (idx < NB) {
        int r = idx;
        int j = r / BSZ, b = r % BSZ;
        float a = 1.f;
        int cnt = 0;
        #pragma unroll
        for (int l = 0; l < LLEN; l++) {
            g_mask[(j * LLEN + l) * BSZ + b] = (a > 0.f) ? 0.f : NEGV;
            cnt += (a > 0.f) ? 1 : 0;
            a *= (inputs[(j * LLEN + l) * BSZ + b] != VSZ) ? 1.f : 0.f;
        }
        g_idx[r] = cnt - 1;
    }
}

// ================= persistent fused LSTM chain (mma.sync) =================
// 128 CTAs (16 n-tiles x 8 m-tiles), CTA tile 256x128, 512 threads (16 warps 8x2,
// warp tile 32x64). 3-stage cp.async, c tile in SMEM, token-major WihT epilogue.
// Per-m-tile sub-barrier (16 CTAs); h staged in SMEM, stored as 4x8-bf16/row.
__global__ __launch_bounds__(512, 1)
void chain_kernel(const int* __restrict__ inputs, const int* __restrict__ target,
                  const float* __restrict__ enc_c0, const float* __restrict__ dec_c0) {
    constexpr int BM = 256, BN = 128, BK = 32, K = HSZ;
    constexpr int AST = 40;
    constexpr int MT = 2, NTc = 8;
    constexpr int STAGE = (BM + BN) * AST;        // 15360 bf16
    constexpr int NSTAGE = 3;
    constexpr int NIT = K / BK;                   // 16

    extern __shared__ __nv_bfloat16 smd[];
    float* c_s = (float*)(smd + NSTAGE * STAGE);               // [32 h][256 rows] = 32 KB
    __nv_bfloat16* hst = (__nv_bfloat16*)(c_s + 32 * 256);     // [256 rows][32 h] = 16 KB
    const uint32_t smbase = (uint32_t)__cvta_generic_to_shared(smd);

    const int tid = threadIdx.x;
    const int warp = tid >> 5, lane = tid & 31;
    const int wm = warp >> 1;                     // 0..7
    const int wn = warp & 1;                      // 0..1
    const int m0 = blockIdx.y * BM, n0 = blockIdx.x * BN;
    const unsigned FULL = 0xffffffffu;
    unsigned int* mybar = &g_bars[blockIdx.y];

    for (int i = tid; i < 32 * 256; i += 512)
        c_s[i] = enc_c0[blockIdx.x * 32 + (i >> 8)];
    __syncthreads();

    for (int t = 0; t < LLEN + TLEN; t++) {
        const bool enc = t < LLEN;
        const __nv_bfloat16* Bw = enc ? g_WhhPE : g_WhhPD;
        const float* WihT = enc ? g_WihTE : g_WihTD;
        const __nv_bfloat16* A;
        int gather = 0;
        if (t == 0)            A = g_hbf;
        else if (t < LLEN)     A = g_Hs + (size_t)(t - 1) * NBH;
        else if (t == LLEN)  { A = g_Hs; gather = 1; }
        else                   A = g_Hd + (size_t)(t - LLEN - 1) * NBH;
        __nv_bfloat16* Hout = enc ? (g_Hs + (size_t)t * NBH)
                                  : (g_Hd + (size_t)(t - LLEN) * NBH);
        int tokmode; const int* tokp = nullptr;
        if (t < LLEN)      { tokmode = 1; tokp = inputs + t * BSZ; }
        else if (t == LLEN)  tokmode = 0;
        else               { tokmode = 2; tokp = target + (t - LLEN - 1) * BSZ; }

        if (t == LLEN) {      // decoder init: reset c
            for (int i = tid; i < 32 * 256; i += 512)
                c_s[i] = dec_c0[blockIdx.x * 32 + (i >> 8)];
            __syncthreads();
        }

        float acc[MT][NTc][4];
        #pragma unroll
        for (int mt = 0; mt < MT; mt++)
            #pragma unroll
            for (int nt = 0; nt < NTc; nt++)
                #pragma unroll
                for (int q = 0; q < 4; q++) acc[mt][nt][q] = 0.f;

        auto load_stage = [&](int it) {
            const int k0 = it * BK;
            const uint32_t base = smbase + (uint32_t)(it % NSTAGE) * STAGE * 2;
            #pragma unroll
            for (int ii = 0; ii < (BM + BN) * 4 / 512; ii++) {
                int c = tid + ii * 512;
                bool isB = c >= BM * 4;
                int cc = isB ? c - BM * 4 : c;
                int row = cc >> 2, part = cc & 3;
                const __nv_bfloat16* src;
                if (isB) {
                    src = Bw + (size_t)(n0 + row) * K + k0 + part * 8;
                } else if (gather) {
                    int rg2 = m0 + row;
                    src = g_Hs + ((size_t)g_idx[rg2] * NB + rg2) * HSZ + k0 + part * 8;
                } else {
                    src = A + (size_t)(m0 + row) * K + k0 + part * 8;
                }
                uint32_t dst = base + (uint32_t)(((isB ? BM + row : row) * AST + part * 8) * 2);
                cp_async16(dst, src);
            }
            cp_commit();
        };

        load_stage(0);
        load_stage(1);

        for (int it = 0; it < NIT; it++) {
            if (it == NIT - 1) cp_wait<0>(); else cp_wait<1>();
            __syncthreads();
            if (it + 2 < NIT) load_stage(it + 2);

            const uint32_t aBase = smbase + (uint32_t)(it % NSTAGE) * STAGE * 2;
            const uint32_t bBase = aBase + BM * AST * 2;

            #pragma unroll
            for (int kk = 0; kk < 2; kk++) {
                uint32_t a[MT][4];
                #pragma unroll
                for (int mt = 0; mt < MT; mt++) {
                    int row = wm * 32 + mt * 16 + (lane & 15);
                    int col = kk * 16 + (lane >> 4) * 8;
                    ldm_x4(a[mt][0], a[mt][1], a[mt][2], a[mt][3],
                           aBase + (uint32_t)((row * AST + col) * 2));
                }
                uint32_t b[NTc][2];
                #pragma unroll
                for (int ntp = 0; ntp < NTc / 2; ntp++) {
                    int row = wn * 64 + ntp * 16 + ((lane >> 4) << 3) + (lane & 7);
                    int col = kk * 16 + ((lane >> 3) & 1) * 8;
                    ldm_x4(b[2 * ntp][0], b[2 * ntp][1], b[2 * ntp + 1][0], b[2 * ntp + 1][1],
                           bBase + (uint32_t)((row * AST + col) * 2));
                }
                #pragma unroll
                for (int mt = 0; mt < MT; mt++)
                    #pragma unroll
                    for (int nt = 0; nt < NTc; nt++) {
                        asm volatile(
                            "mma.sync.aligned.m16n8k16.row.col.f32.bf16.bf16.f32 "
                            "{%0,%1,%2,%3}, {%4,%5,%6,%7}, {%8,%9}, {%0,%1,%2,%3};"
                            : "+f"(acc[mt][nt][0]), "+f"(acc[mt][nt][1]),
                              "+f"(acc[mt][nt][2]), "+f"(acc[mt][nt][3])
                            : "r"(a[mt][0]), "r"(a[mt][1]), "r"(a[mt][2]), "r"(a[mt][3]),
                              "r"(b[nt][0]), "r"(b[nt][1]));
                    }
            }
        }
        __syncthreads();

        // -------- fused LSTM epilogue (h staged in SMEM) --------
        #pragma unroll
        for (int mt = 0; mt < MT; mt++) {
            int rl_lo = wm * 32 + mt * 16 + (lane >> 2);
            int rl_hi = rl_lo + 8;
            int r_lo = m0 + rl_lo, r_hi = m0 + rl_hi;
            int tok_lo = VSZ, tok_hi = VSZ;
            if (tokmode == 1) {
                tok_lo = tokp[(r_lo / BSZ) * (LLEN * BSZ) + (r_lo % BSZ)];
                tok_hi = tokp[(r_hi / BSZ) * (LLEN * BSZ) + (r_hi % BSZ)];
            } else if (tokmode == 2) {
                tok_lo = tokp[r_lo % BSZ];
                tok_hi = tokp[r_hi % BSZ];
            }
            const float* wl = WihT + (size_t)tok_lo * H4SZ;
            const float* wh_ = WihT + (size_t)tok_hi * H4SZ;
            #pragma unroll
            for (int nt = 0; nt < NTc; nt++) {
                int c0 = n0 + wn * 64 + nt * 8 + 2 * (lane & 3);
                float2 el = *(const float2*)&wl[c0];
                float2 eh = *(const float2*)&wh_[c0];
                float v00 = acc[mt][nt][0] + el.x;
                float v01 = acc[mt][nt][1] + el.y;
                float v10 = acc[mt][nt][2] + eh.x;
                float v11 = acc[mt][nt][3] + eh.y;
                float p00 = __shfl_xor_sync(FULL, v00, 1);
                float p01 = __shfl_xor_sync(FULL, v01, 1);
                float p10 = __shfl_xor_sync(FULL, v10, 1);
                float p11 = __shfl_xor_sync(FULL, v11, 1);
                if ((lane & 1) == 0) {
                    int hl = wn * 16 + nt * 2 + ((lane & 3) >> 1);
                    {
                        float cold = c_s[hl * 256 + rl_lo];
                        float c2 = sigmoidf_(v01) * cold + sigmoidf_(v00) * tanhf(p00);
                        float h2 = sigmoidf_(p01) * tanhf(c2);
                        c_s[hl * 256 + rl_lo] = c2;
                        hst[rl_lo * 32 + hl] = __float2bfloat16_rn(h2);
                    }
                    {
                        float cold = c_s[hl * 256 + rl_hi];
                        float c2 = sigmoidf_(v11) * cold + sigmoidf_(v10) * tanhf(p10);
                        float h2 = sigmoidf_(p11) * tanhf(c2);
                        c_s[hl * 256 + rl_hi] = c2;
                        hst[rl_hi * 32 + hl] = __float2bfloat16_rn(h2);
                    }
                }
            }
        }
        __syncthreads();

        // coalesced h store: 4 chunks of 8 bf16 (16B) per row, 1024 chunks / 512 threads
        #pragma unroll
        for (int i = tid; i < 256 * 4; i += 512) {
            int row = i >> 2, q = i & 3;
            uint4 v = *(const uint4*)&hst[row * 32 + q * 8];
            *(uint4*)&Hout[(size_t)(m0 + row) * HSZ + blockIdx.x * 32 + q * 8] = v;
        }

        // -------- per-m-tile sub-barrier (16 CTAs) --------
        __threadfence();
        __syncthreads();
        if (tid == 0) {
            atomicAdd(mybar, 1u);
            unsigned need = 16u * (unsigned)(t + 1);
            while (*(volatile unsigned*)mybar < need) { }
        }
        __syncthreads();
        __threadfence();
    }
}

// ================= generic bf16 GEMM (batched tail) =================
// MODE 2: tanh(+b1) f32 store; MODE 4: bf16 store
template<int MODE>
__global__ __launch_bounds__(256)
void bf16_gemm_kernel(const __nv_bfloat16* __restrict__ A, const __nv_bfloat16* __restrict__ Bw,
                      void* __restrict__ Cv, int M, int N, int K,
                      const float* __restrict__ b1) {
    constexpr int BM = 128, BN = 128, BK = 32;
    constexpr int AST = 40;
    constexpr int MT = 2, NTc = 8;
    constexpr int STAGE = (BM + BN) * AST;

    __shared__ __nv_bfloat16 sm[2 * STAGE];
    const uint32_t smbase = (uint32_t)__cvta_generic_to_shared(sm);

    const int tid = threadIdx.x;
    const int warp = tid >> 5, lane = tid & 31;
    const int wm = warp >> 1;
    const int wn = warp & 1;
    const int m0 = blockIdx.y * BM, n0 = blockIdx.x * BN;
    const int NIT = K / BK;

    float acc[MT][NTc][4];
    #pragma unroll
    for (int mt = 0; mt < MT; mt++)
        #pragma unroll
        for (int nt = 0; nt < NTc; nt++)
            #pragma unroll
            for (int q = 0; q < 4; q++) acc[mt][nt][q] = 0.f;

    auto load_stage = [&](int it, int buf) {
        const int k0 = it * BK;
        const uint32_t base = smbase + (uint32_t)buf * STAGE * 2;
        #pragma unroll
        for (int c = tid; c < (BM + BN) * 4; c += 256) {
            bool isB = c >= BM * 4;
            int cc = isB ? c - BM * 4 : c;
            int row = cc >> 2, part = cc & 3;
            const __nv_bfloat16* src = isB
                ? (Bw + (size_t)(n0 + row) * K + k0 + part * 8)
                : (A  + (size_t)(m0 + row) * K + k0 + part * 8);
            uint32_t dst = base + (uint32_t)(((isB ? BM + row : row) * AST + part * 8) * 2);
            cp_async16(dst, src);
        }
    };

    load_stage(0, 0);
    cp_commit();

    for (int it = 0; it < NIT; it++) {
        if (it + 1 < NIT) { load_stage(it + 1, (it + 1) & 1); cp_commit(); cp_wait<1>(); }
        else              { cp_wait<0>(); }
        __syncthreads();

        const uint32_t aBase = smbase + (uint32_t)(it & 1) * STAGE * 2;
        const uint32_t bBase = aBase + BM * AST * 2;

        #pragma unroll
        for (int kk = 0; kk < 2; kk++) {
            uint32_t a[MT][4];
            #pragma unroll
            for (int mt = 0; mt < MT; mt++) {
                int row = wm * 32 + mt * 16 + (lane & 15);
                int col = kk * 16 + (lane >> 4) * 8;
                ldm_x4(a[mt][0], a[mt][1], a[mt][2], a[mt][3],
                       aBase + (uint32_t)((row * AST + col) * 2));
            }
            uint32_t b[NTc][2];
            #pragma unroll
            for (int ntp = 0; ntp < NTc / 2; ntp++) {
                int row = wn * 64 + ntp * 16 + ((lane >> 4) << 3) + (lane & 7);
                int col = kk * 16 + ((lane >> 3) & 1) * 8;
                ldm_x4(b[2 * ntp][0], b[2 * ntp][1], b[2 * ntp + 1][0], b[2 * ntp + 1][1],
                       bBase + (uint32_t)((row * AST + col) * 2));
            }
            #pragma unroll
            for (int mt = 0; mt < MT; mt++)
                #pragma unroll
                for (int nt = 0; nt < NTc; nt++) {
                    asm volatile(
                        "mma.sync.aligned.m16n8k16.row.col.f32.bf16.bf16.f32 "
                        "{%0,%1,%2,%3}, {%4,%5,%6,%7}, {%8,%9}, {%0,%1,%2,%3};"
                        : "+f"(acc[mt][nt][0]), "+f"(acc[mt][nt][1]),
                          "+f"(acc[mt][nt][2]), "+f"(acc[mt][nt][3])
                        : "r"(a[mt][0]), "r"(a[mt][1]), "r"(a[mt][2]), "r"(a[mt][3]),
                          "r"(b[nt][0]), "r"(b[nt][1]));
                }
        }
        __syncthreads();
    }

    float* Cf = (float*)Cv;
    __nv_bfloat16* Cb = (__nv_bfloat16*)Cv;
    #pragma unroll
    for (int mt = 0; mt < MT; mt++) {
        int r_lo = m0 + wm * 32 + mt * 16 + (lane >> 2);
        int r_hi = r_lo + 8;
        #pragma unroll
        for (int nt = 0; nt < NTc; nt++) {
            int c0 = n0 + wn * 64 + nt * 8 + 2 * (lane & 3);
            float v00 = acc[mt][nt][0], v01 = acc[mt][nt][1];
            float v10 = acc[mt][nt][2], v11 = acc[mt][nt][3];
            if (MODE == 2) {
                float bb0 = b1[c0], bb1 = b1[c0 + 1];
                v00 = tanhf(v00 + bb0); v01 = tanhf(v01 + bb1);
                v10 = tanhf(v10 + bb0); v11 = tanhf(v11 + bb1);
            }
            if (MODE == 4) {
                __nv_bfloat162 lo = __floats2bfloat162_rn(v00, v01);
                __nv_bfloat162 hi = __floats2bfloat162_rn(v10, v11);
                *(__nv_bfloat162*)&Cb[(size_t)r_lo * N + c0] = lo;
                *(__nv_bfloat162*)&Cb[(size_t)r_hi * N + c0] = hi;
            } else {
                Cf[(size_t)r_lo * N + c0] = v00;
                Cf[(size_t)r_lo * N + c0 + 1] = v01;
                Cf[(size_t)r_hi * N + c0] = v10;
                Cf[(size_t)r_hi * N + c0 + 1] = v11;
            }
        }
    }
}

// ---------------- batched attention over all 32 timesteps ----------------
__global__ __launch_bounds__(256) void attn_all_kernel() {
    __shared__ __nv_bfloat16 hs_s[LLEN * HSZ];
    __shared__ float u_s[HSZ];
    __shared__ float sc[LLEN];
    __shared__ float mask_s[LLEN];

    const int r = blockIdx.x;
    const int j = r / BSZ;
    const int tid = threadIdx.x;
    const int warp = tid >> 5, lane = tid & 31;

    #pragma unroll
    for (int idx = tid; idx < LLEN * HSZ / 8; idx += 256) {
        int l = idx >> 6;
        int c8 = (idx & 63) * 8;
        uint4 v = *(const uint4*)&g_Hs[((size_t)l * NB + r) * HSZ + c8];
        *(uint4*)&hs_s[l * HSZ + c8] = v;
    }
    if (tid < LLEN) mask_s[tid] = g_mask[(j * LLEN + tid) * BSZ + (r % BSZ)];
    __syncthreads();

    for (int t = 0; t < TLEN; t++) {
        const size_t row = (size_t)t * NB + r;
        for (int k = tid; k < HSZ; k += 256)
            u_s[k] = __bfloat162float(g_ubf[row * HSZ + k]);
        __syncthreads();

        for (int l = warp; l < LLEN; l += 8) {
            float s = 0.f;
            for (int k = lane; k < HSZ; k += 32)
                s += __bfloat162float(hs_s[l * HSZ + k]) * u_s[k];
            #pragma unroll
            for (int off = 16; off > 0; off >>= 1) s += __shfl_down_sync(0xffffffffu, s, off);
            if (lane == 0) sc[l] = s + mask_s[l];
        }
        __syncthreads();

        if (warp == 0) {
            float v = sc[lane];
            float mx = v;
            #pragma unroll
            for (int off = 16; off > 0; off >>= 1) mx = fmaxf(mx, __shfl_xor_sync(0xffffffffu, mx, off));
            float e = expf(v - mx);
            float ssum = e;
            #pragma unroll
            for (int off = 16; off > 0; off >>= 1) ssum += __shfl_xor_sync(0xffffffffu, ssum, off);
            sc[lane] = e / ssum;
        }
        __syncthreads();

        __nv_bfloat16* hc = g_hcbf + row * (2 * HSZ);
        #pragma unroll
        for (int kq = 0; kq < 2; kq++) {
            int k = tid + kq * 256;
            float cx = 0.f;
            #pragma unroll
            for (int l = 0; l < LLEN; l++) cx += sc[l] * __bfloat162float(hs_s[l * HSZ + k]);
            hc[HSZ + k] = __float2bfloat16_rn(cx);
        }
        if (tid < 64) {
            uint4 v = *(const uint4*)&g_Hd[row * HSZ + tid * 8];
            *(uint4*)&hc[tid * 8] = v;
        }
        __syncthreads();
    }
}

// ---------------- pool + logits + log-softmax + score over all t ----------------
__global__ __launch_bounds__(256) void pool_score_all_kernel(
    const float* __restrict__ Vw, const float* __restrict__ Vb,
    const int* __restrict__ target, float* __restrict__ out) {
    extern __shared__ float dsm[];
    float* Vw_s = dsm;
    float* m_s  = dsm + ESZ * 132;
    float* lgs  = m_s + ESZ;
    __shared__ float red[2];

    const int b = blockIdx.x;
    const int tid = threadIdx.x;
    const int lane = tid & 31;

    for (int idx = tid; idx < V1SZ * ESZ; idx += 256) {
        int v = idx >> 7, e = idx & 127;
        Vw_s[e * 132 + v] = Vw[(size_t)v * ESZ + e];
    }
    __syncthreads();

    float score = 0.f, act = 1.f;
    for (int t = 0; t < TLEN; t++) {
        if (tid < ESZ) {
            const size_t base = ((size_t)t * NB + b) * ESZ + tid;
            float m = g_fc[base];
            #pragma unroll
            for (int jj = 1; jj < NEXN; jj++)
                m = fmaxf(m, g_fc[base + (size_t)jj * BSZ * ESZ]);
            m_s[tid] = m;
        }
        __syncthreads();

        if (tid < V1SZ) {
            float s = Vb[tid];
            #pragma unroll 8
            for (int e = 0; e < ESZ; e++) s += m_s[e] * Vw_s[e * 132 + tid];
            lgs[tid] = s;
        }
        __syncthreads();

        if (tid < 32) {
            float mx = -1e30f;
            for (int v = lane; v < V1SZ; v += 32) mx = fmaxf(mx, lgs[v]);
            #pragma unroll
            for (int off = 16; off > 0; off >>= 1) mx = fmaxf(mx, __shfl_xor_sync(0xffffffffu, mx, off));
            float ssum = 0.f;
            for (int v = lane; v < V1SZ; v += 32) ssum += expf(lgs[v] - mx);
            #pragma unroll
            for (int off = 16; off > 0; off >>= 1) ssum += __shfl_xor_sync(0xffffffffu, ssum, off);
            if (lane == 0) { red[0] = mx; red[1] = ssum; }
        }
        __syncthreads();

        int tg = target[t * BSZ + b];
        float ls = lgs[tg] - red[0] - logf(red[1]);
        score += ls * act;
        act *= (tg != VSZ) ? 1.f : 0.f;
        __syncthreads();
    }
    if (tid == 0) out[b] = score;
}

// ---------------- host orchestration ----------------
extern "C" void kernel_launch(void* const* d_in, const int* in_sizes, int n_in,
                              void* d_out, int out_size) {
    const int*   inputs  = (const int*)  d_in[0];
    const int*   target  = (const int*)  d_in[1];
    const float* enc_Wih = (const float*)d_in[2];
    const float* enc_Whh = (const float*)d_in[3];
    const float* enc_bih = (const float*)d_in[4];
    const float* enc_bhh = (const float*)d_in[5];
    const float* enc_h0  = (const float*)d_in[6];
    const float* enc_c0  = (const float*)d_in[7];
    const float* dec_Wih = (const float*)d_in[8];
    const float* dec_Whh = (const float*)d_in[9];
    const float* dec_bih = (const float*)d_in[10];
    const float* dec_bhh = (const float*)d_in[11];
    const float* dec_c0  = (const float*)d_in[12];
    const float* W_w     = (const float*)d_in[13];
    const float* W_b     = (const float*)d_in[14];
    const float* V_w     = (const float*)d_in[15];
    const float* V_b     = (const float*)d_in[16];
    const float* A_w     = (const float*)d_in[17];
    float* out = (float*)d_out;

    __nv_bfloat16 *WhhPE_p, *WhhPD_p, *Awb_p, *Wwb_p, *hcbf_p, *Hd_p, *ubf_p;
    float *fc_p;
    cudaGetSymbolAddress((void**)&WhhPE_p, g_WhhPE);
    cudaGetSymbolAddress((void**)&WhhPD_p, g_WhhPD);
    cudaGetSymbolAddress((void**)&Awb_p, g_Awb);
    cudaGetSymbolAddress((void**)&Wwb_p, g_Wwb);
    cudaGetSymbolAddress((void**)&hcbf_p, g_hcbf);
    cudaGetSymbolAddress((void**)&Hd_p, g_Hd);
    cudaGetSymbolAddress((void**)&ubf_p, g_ubf);
    cudaGetSymbolAddress((void**)&fc_p, g_fc);

    const int ps_smem = (ESZ * 132 + ESZ + 132) * (int)sizeof(float);
    cudaFuncSetAttribute(pool_score_all_kernel, cudaFuncAttributeMaxDynamicSharedMemorySize, ps_smem);
    const int chain_smem = 3 * (256 + 128) * 40 * 2 + 32 * 256 * 4 + 256 * 32 * 2;
    cudaFuncSetAttribute(chain_kernel, cudaFuncAttributeMaxDynamicSharedMemorySize, chain_smem);

    // ---- prep ----
    permute_whh_kernel<<<H4SZ, 256>>>(enc_Whh, WhhPE_p);
    permute_whh_kernel<<<H4SZ, 256>>>(dec_Whh, WhhPD_p);
    transpose_wih_both_kernel<<<dim3(V1SZ, 2), 256>>>(enc_Wih, enc_bih, enc_bhh,
                                                      dec_Wih, dec_bih, dec_bhh);
    convert_both_kernel<<<(HSZ * HSZ + 255) / 256, 256>>>(A_w, W_w);
    init_all_kernel<<<(NB * HSZ + 255) / 256, 256>>>(enc_h0, inputs);

    // ---- persistent LSTM chain ----
    chain_kernel<<<dim3(H4SZ / 128, NB / 256), 512, chain_smem>>>(
        inputs, target, enc_c0, dec_c0);

    // ---- batched decoder tail ----
    bf16_gemm_kernel<4><<<dim3(HSZ / 128, NT_ALL / 128), 256>>>(
        Hd_p, Awb_p, (void*)ubf_p, NT_ALL, HSZ, HSZ, nullptr);
    attn_all_kernel<<<NB, 256>>>();
    bf16_gemm_kernel<2><<<dim3(ESZ / 128, NT_ALL / 128), 256>>>(
        hcbf_p, Wwb_p, (void*)fc_p, NT_ALL, ESZ, 2 * HSZ, W_b);
    pool_score_all_kernel<<<BSZ, 256, ps_smem>>>(V_w, V_b, target, out);
}

// round 16
// speedup vs baseline: 1.0147x; 1.0109x over previous
#include <cuda_runtime.h>
#include <cuda_bf16.h>
#include <math.h>
#include <stdint.h>

// ---------------- problem constants ----------------
#define VSZ   128
#define V1SZ  129
#define HSZ   512
#define H4SZ  2048
#define ESZ   128
#define NEXN  4
#define LLEN  32
#define BSZ   512
#define TLEN  32
#define NB    (NEXN * BSZ)      // 2048
#define NT_ALL (TLEN * NB)      // 65536
#define NEGV  (-1e9f)
#define NBH   ((size_t)NB * HSZ)
#define NU    (HSZ + ESZ)       // 640 stacked B rows for combined GEMM

// ---------------- device scratch (allocation-free) ----------------
__device__ __nv_bfloat16 g_Hs[(size_t)LLEN * NB * HSZ];
__device__ __nv_bfloat16 g_Hd[(size_t)TLEN * NB * HSZ];
__device__ __nv_bfloat16 g_hbf[NB * HSZ];
__device__ __nv_bfloat16 g_ubf[(size_t)NT_ALL * HSZ];       // u (bf16)
__device__ float g_fch[(size_t)NT_ALL * ESZ];               // h @ Ww1^T (f32, 32 MB)
__device__ __nv_bfloat16 g_ctx[(size_t)NT_ALL * HSZ];       // ctx (bf16, 64 MB)
__device__ float g_fc[(size_t)NT_ALL * ESZ];
__device__ float g_mask[NEXN * LLEN * BSZ];
__device__ int   g_idx[NB];
__device__ unsigned int g_bar;
__device__ __nv_bfloat16 g_WhhPE[H4SZ * HSZ];
__device__ __nv_bfloat16 g_WhhPD[H4SZ * HSZ];
__device__ float g_WihTE[V1SZ * H4SZ];
__device__ float g_WihTD[V1SZ * H4SZ];
__device__ __nv_bfloat16 g_Bu[NU * HSZ];                    // [A_w ; Ww1] stacked (bf16)
__device__ __nv_bfloat16 g_Ww2b[ESZ * HSZ];                 // W_w[:,512:] (bf16)

__device__ __forceinline__ float sigmoidf_(float x) { return 1.f / (1.f + expf(-x)); }

// ---------------- ptx helpers ----------------
__device__ __forceinline__ void cp_async16(uint32_t dst, const void* src) {
    asm volatile("cp.async.cg.shared.global [%0], [%1], 16;\n" :: "r"(dst), "l"(src));
}
__device__ __forceinline__ void cp_commit() { asm volatile("cp.async.commit_group;\n"); }
template<int N> __device__ __forceinline__ void cp_wait() {
    asm volatile("cp.async.wait_group %0;\n" :: "n"(N));
}
__device__ __forceinline__ void ldm_x4(uint32_t& r0, uint32_t& r1, uint32_t& r2, uint32_t& r3,
                                       uint32_t addr) {
    asm volatile("ldmatrix.sync.aligned.m8n8.x4.shared.b16 {%0,%1,%2,%3}, [%4];"
                 : "=r"(r0), "=r"(r1), "=r"(r2), "=r"(r3) : "r"(addr));
}

// ---------------- prep kernels ----------------
__global__ void permute_whh_kernel(const float* __restrict__ Whh,
                                   __nv_bfloat16* __restrict__ WhhP) {
    int np = blockIdx.x;
    int h = np >> 2, g = np & 3;
    int orig = g * HSZ + h;
    for (int k = threadIdx.x; k < HSZ; k += 256)
        WhhP[np * HSZ + k] = __float2bfloat16_rn(Whh[(size_t)orig * HSZ + k]);
}

__global__ void transpose_wih_both_kernel(
    const float* __restrict__ WihE, const float* __restrict__ bihE, const float* __restrict__ bhhE,
    const float* __restrict__ WihD, const float* __restrict__ bihD, const float* __restrict__ bhhD) {
    int v = blockIdx.x;
    const float* Wih = blockIdx.y ? WihD : WihE;
    const float* bih = blockIdx.y ? bihD : bihE;
    const float* bhh = blockIdx.y ? bhhD : bhhE;
    float* WihT = blockIdx.y ? g_WihTD : g_WihTE;
    for (int np = threadIdx.x; np < H4SZ; np += 256) {
        int h = np >> 2, g = np & 3;
        int orig = g * HSZ + h;
        WihT[(size_t)v * H4SZ + np] = Wih[(size_t)orig * V1SZ + v] + bih[orig] + bhh[orig];
    }
}

// build stacked [A_w ; Ww1] (bf16) and Ww2 (bf16)
__global__ void build_tail_weights_kernel(const float* __restrict__ Aw,
                                          const float* __restrict__ Ww) {
    int i = blockIdx.x * blockDim.x + threadIdx.x;
    if (i < NU * HSZ) {
        int row = i / HSZ, k = i % HSZ;
        float v = (row < HSZ) ? Aw[(size_t)row * HSZ + k]
                              : Ww[(size_t)(row - HSZ) * (2 * HSZ) + k];
        g_Bu[i] = __float2bfloat16_rn(v);
    }
    if (i < ESZ * HSZ) {
        int e = i / HSZ, k = i % HSZ;
        g_Ww2b[i] = __float2bfloat16_rn(Ww[(size_t)e * (2 * HSZ) + HSZ + k]);
    }
}

__global__ void init_all_kernel(const float* __restrict__ h0, const int* __restrict__ inputs) {
    int idx = blockIdx.x * blockDim.x + threadIdx.x;
    if (idx == 0) g_bar = 0u;
    if (idx < NB * HSZ) g_hbf[idx] = __float2bfloat16_rn(h0[idx & (HSZ - 1)]);
    if (idx < NB) {
        int r = idx;
        int j = r / BSZ, b = r % BSZ;
        float a = 1.f;
        int cnt = 0;
        #pragma unroll
        for (int l = 0; l < LLEN; l++) {
            g_mask[(j * LLEN + l) * BSZ + b] = (a > 0.f) ? 0.f : NEGV;
            cnt += (a > 0.f) ? 1 : 0;
            a *= (inputs[(j * LLEN + l) * BSZ + b] != VSZ) ? 1.f : 0.f;
        }
        g_idx[r] = cnt - 1;
    }
}

// ================= persistent fused LSTM chain (R12 config, best known) =================
__global__ __launch_bounds__(512, 1)
void chain_kernel(const int* __restrict__ inputs, const int* __restrict__ target,
                  const float* __restrict__ enc_c0, const float* __restrict__ dec_c0) {
    constexpr int BM = 256, BN = 128, BK = 32, K = HSZ;
    constexpr int AST = 40;
    constexpr int MT = 2, NTc = 8;
    constexpr int STAGE = (BM + BN) * AST;
    constexpr int NSTAGE = 3;
    constexpr int NIT = K / BK;
    constexpr int NCTA = 128;

    extern __shared__ __nv_bfloat16 smd[];
    float* c_s = (float*)(smd + NSTAGE * STAGE);
    const uint32_t smbase = (uint32_t)__cvta_generic_to_shared(smd);

    const int tid = threadIdx.x;
    const int warp = tid >> 5, lane = tid & 31;
    const int wm = warp >> 1;
    const int wn = warp & 1;
    const int m0 = blockIdx.y * BM, n0 = blockIdx.x * BN;
    const unsigned FULL = 0xffffffffu;

    for (int i = tid; i < 32 * 256; i += 512)
        c_s[i] = enc_c0[blockIdx.x * 32 + (i >> 8)];
    __syncthreads();

    for (int t = 0; t < LLEN + TLEN; t++) {
        const bool enc = t < LLEN;
        const __nv_bfloat16* Bw = enc ? g_WhhPE : g_WhhPD;
        const float* WihT = enc ? g_WihTE : g_WihTD;
        const __nv_bfloat16* A;
        int gather = 0;
        if (t == 0)            A = g_hbf;
        else if (t < LLEN)     A = g_Hs + (size_t)(t - 1) * NBH;
        else if (t == LLEN)  { A = g_Hs; gather = 1; }
        else                   A = g_Hd + (size_t)(t - LLEN - 1) * NBH;
        __nv_bfloat16* Hout = enc ? (g_Hs + (size_t)t * NBH)
                                  : (g_Hd + (size_t)(t - LLEN) * NBH);
        int tokmode; const int* tokp = nullptr;
        if (t < LLEN)      { tokmode = 1; tokp = inputs + t * BSZ; }
        else if (t == LLEN)  tokmode = 0;
        else               { tokmode = 2; tokp = target + (t - LLEN - 1) * BSZ; }

        if (t == LLEN) {
            for (int i = tid; i < 32 * 256; i += 512)
                c_s[i] = dec_c0[blockIdx.x * 32 + (i >> 8)];
            __syncthreads();
        }

        float acc[MT][NTc][4];
        #pragma unroll
        for (int mt = 0; mt < MT; mt++)
            #pragma unroll
            for (int nt = 0; nt < NTc; nt++)
                #pragma unroll
                for (int q = 0; q < 4; q++) acc[mt][nt][q] = 0.f;

        auto load_stage = [&](int it) {
            const int k0 = it * BK;
            const uint32_t base = smbase + (uint32_t)(it % NSTAGE) * STAGE * 2;
            #pragma unroll
            for (int ii = 0; ii < (BM + BN) * 4 / 512; ii++) {
                int c = tid + ii * 512;
                bool isB = c >= BM * 4;
                int cc = isB ? c - BM * 4 : c;
                int row = cc >> 2, part = cc & 3;
                const __nv_bfloat16* src;
                if (isB) {
                    src = Bw + (size_t)(n0 + row) * K + k0 + part * 8;
                } else if (gather) {
                    int rg2 = m0 + row;
                    src = g_Hs + ((size_t)g_idx[rg2] * NB + rg2) * HSZ + k0 + part * 8;
                } else {
                    src = A + (size_t)(m0 + row) * K + k0 + part * 8;
                }
                uint32_t dst = base + (uint32_t)(((isB ? BM + row : row) * AST + part * 8) * 2);
                cp_async16(dst, src);
            }
            cp_commit();
        };

        load_stage(0);
        load_stage(1);

        for (int it = 0; it < NIT; it++) {
            if (it == NIT - 1) cp_wait<0>(); else cp_wait<1>();
            __syncthreads();
            if (it + 2 < NIT) load_stage(it + 2);

            const uint32_t aBase = smbase + (uint32_t)(it % NSTAGE) * STAGE * 2;
            const uint32_t bBase = aBase + BM * AST * 2;

            #pragma unroll
            for (int kk = 0; kk < 2; kk++) {
                uint32_t a[MT][4];
                #pragma unroll
                for (int mt = 0; mt < MT; mt++) {
                    int row = wm * 32 + mt * 16 + (lane & 15);
                    int col = kk * 16 + (lane >> 4) * 8;
                    ldm_x4(a[mt][0], a[mt][1], a[mt][2], a[mt][3],
                           aBase + (uint32_t)((row * AST + col) * 2));
                }
                uint32_t b[NTc][2];
                #pragma unroll
                for (int ntp = 0; ntp < NTc / 2; ntp++) {
                    int row = wn * 64 + ntp * 16 + ((lane >> 4) << 3) + (lane & 7);
                    int col = kk * 16 + ((lane >> 3) & 1) * 8;
                    ldm_x4(b[2 * ntp][0], b[2 * ntp][1], b[2 * ntp + 1][0], b[2 * ntp + 1][1],
                           bBase + (uint32_t)((row * AST + col) * 2));
                }
                #pragma unroll
                for (int mt = 0; mt < MT; mt++)
                    #pragma unroll
                    for (int nt = 0; nt < NTc; nt++) {
                        asm volatile(
                            "mma.sync.aligned.m16n8k16.row.col.f32.bf16.bf16.f32 "
                            "{%0,%1,%2,%3}, {%4,%5,%6,%7}, {%8,%9}, {%0,%1,%2,%3};"
                            : "+f"(acc[mt][nt][0]), "+f"(acc[mt][nt][1]),
                              "+f"(acc[mt][nt][2]), "+f"(acc[mt][nt][3])
                            : "r"(a[mt][0]), "r"(a[mt][1]), "r"(a[mt][2]), "r"(a[mt][3]),
                              "r"(b[nt][0]), "r"(b[nt][1]));
                    }
            }
        }
        __syncthreads();

        // -------- fused LSTM epilogue --------
        #pragma unroll
        for (int mt = 0; mt < MT; mt++) {
            int rl_lo = wm * 32 + mt * 16 + (lane >> 2);
            int rl_hi = rl_lo + 8;
            int r_lo = m0 + rl_lo, r_hi = m0 + rl_hi;
            int tok_lo = VSZ, tok_hi = VSZ;
            if (tokmode == 1) {
                tok_lo = tokp[(r_lo / BSZ) * (LLEN * BSZ) + (r_lo % BSZ)];
                tok_hi = tokp[(r_hi / BSZ) * (LLEN * BSZ) + (r_hi % BSZ)];
            } else if (tokmode == 2) {
                tok_lo = tokp[r_lo % BSZ];
                tok_hi = tokp[r_hi % BSZ];
            }
            const float* wl = WihT + (size_t)tok_lo * H4SZ;
            const float* wh_ = WihT + (size_t)tok_hi * H4SZ;
            #pragma unroll
            for (int nt = 0; nt < NTc; nt++) {
                int c0 = n0 + wn * 64 + nt * 8 + 2 * (lane & 3);
                float2 el = *(const float2*)&wl[c0];
                float2 eh = *(const float2*)&wh_[c0];
                float v00 = acc[mt][nt][0] + el.x;
                float v01 = acc[mt][nt][1] + el.y;
                float v10 = acc[mt][nt][2] + eh.x;
                float v11 = acc[mt][nt][3] + eh.y;
                float p00 = __shfl_xor_sync(FULL, v00, 1);
                float p01 = __shfl_xor_sync(FULL, v01, 1);
                float p10 = __shfl_xor_sync(FULL, v10, 1);
                float p11 = __shfl_xor_sync(FULL, v11, 1);
                if ((lane & 1) == 0) {
                    int hl = wn * 16 + nt * 2 + ((lane & 3) >> 1);
                    int hg = blockIdx.x * 32 + hl;
                    {
                        float cold = c_s[hl * 256 + rl_lo];
                        float c2 = sigmoidf_(v01) * cold + sigmoidf_(v00) * tanhf(p00);
                        float h2 = sigmoidf_(p01) * tanhf(c2);
                        c_s[hl * 256 + rl_lo] = c2;
                        Hout[(size_t)r_lo * HSZ + hg] = __float2bfloat16_rn(h2);
                    }
                    {
                        float cold = c_s[hl * 256 + rl_hi];
                        float c2 = sigmoidf_(v11) * cold + sigmoidf_(v10) * tanhf(p10);
                        float h2 = sigmoidf_(p11) * tanhf(c2);
                        c_s[hl * 256 + rl_hi] = c2;
                        Hout[(size_t)r_hi * HSZ + hg] = __float2bfloat16_rn(h2);
                    }
                }
            }
        }

        // -------- grid barrier --------
        __threadfence();
        __syncthreads();
        if (tid == 0) {
            atomicAdd(&g_bar, 1u);
            unsigned need = (unsigned)NCTA * (unsigned)(t + 1);
            while (*(volatile unsigned*)&g_bar < need) { }
        }
        __syncthreads();
        __threadfence();
    }
}

// ================= generic bf16 GEMM (batched tail) =================
// MODE 5: combined u+fch store (cols<512 -> bf16 u; cols>=512 -> f32 fch)
// MODE 6: fc = tanh(acc + fch + b1)
template<int MODE>
__global__ __launch_bounds__(256)
void bf16_gemm_kernel(const __nv_bfloat16* __restrict__ A, const __nv_bfloat16* __restrict__ Bw,
                      void* __restrict__ Cv, int M, int N, int K,
                      const float* __restrict__ b1, const float* __restrict__ aux) {
    constexpr int BM = 128, BN = 128, BK = 32;
    constexpr int AST = 40;
    constexpr int MT = 2, NTc = 8;
    constexpr int STAGE = (BM + BN) * AST;

    __shared__ __nv_bfloat16 sm[2 * STAGE];
    const uint32_t smbase = (uint32_t)__cvta_generic_to_shared(sm);

    const int tid = threadIdx.x;
    const int warp = tid >> 5, lane = tid & 31;
    const int wm = warp >> 1;
    const int wn = warp & 1;
    const int m0 = blockIdx.y * BM, n0 = blockIdx.x * BN;
    const int NIT = K / BK;

    float acc[MT][NTc][4];
    #pragma unroll
    for (int mt = 0; mt < MT; mt++)
        #pragma unroll
        for (int nt = 0; nt < NTc; nt++)
            #pragma unroll
            for (int q = 0; q < 4; q++) acc[mt][nt][q] = 0.f;

    auto load_stage = [&](int it, int buf) {
        const int k0 = it * BK;
        const uint32_t base = smbase + (uint32_t)buf * STAGE * 2;
        #pragma unroll
        for (int c = tid; c < (BM + BN) * 4; c += 256) {
            bool isB = c >= BM * 4;
            int cc = isB ? c - BM * 4 : c;
            int row = cc >> 2, part = cc & 3;
            const __nv_bfloat16* src = isB
                ? (Bw + (size_t)(n0 + row) * K + k0 + part * 8)
                : (A  + (size_t)(m0 + row) * K + k0 + part * 8);
            uint32_t dst = base + (uint32_t)(((isB ? BM + row : row) * AST + part * 8) * 2);
            cp_async16(dst, src);
        }
    };

    load_stage(0, 0);
    cp_commit();

    for (int it = 0; it < NIT; it++) {
        if (it + 1 < NIT) { load_stage(it + 1, (it + 1) & 1); cp_commit(); cp_wait<1>(); }
        else              { cp_wait<0>(); }
        __syncthreads();

        const uint32_t aBase = smbase + (uint32_t)(it & 1) * STAGE * 2;
        const uint32_t bBase = aBase + BM * AST * 2;

        #pragma unroll
        for (int kk = 0; kk < 2; kk++) {
            uint32_t a[MT][4];
            #pragma unroll
            for (int mt = 0; mt < MT; mt++) {
                int row = wm * 32 + mt * 16 + (lane & 15);
                int col = kk * 16 + (lane >> 4) * 8;
                ldm_x4(a[mt][0], a[mt][1], a[mt][2], a[mt][3],
                       aBase + (uint32_t)((row * AST + col) * 2));
            }
            uint32_t b[NTc][2];
            #pragma unroll
            for (int ntp = 0; ntp < NTc / 2; ntp++) {
                int row = wn * 64 + ntp * 16 + ((lane >> 4) << 3) + (lane & 7);
                int col = kk * 16 + ((lane >> 3) & 1) * 8;
                ldm_x4(b[2 * ntp][0], b[2 * ntp][1], b[2 * ntp + 1][0], b[2 * ntp + 1][1],
                       bBase + (uint32_t)((row * AST + col) * 2));
            }
            #pragma unroll
            for (int mt = 0; mt < MT; mt++)
                #pragma unroll
                for (int nt = 0; nt < NTc; nt++) {
                    asm volatile(
                        "mma.sync.aligned.m16n8k16.row.col.f32.bf16.bf16.f32 "
                        "{%0,%1,%2,%3}, {%4,%5,%6,%7}, {%8,%9}, {%0,%1,%2,%3};"
                        : "+f"(acc[mt][nt][0]), "+f"(acc[mt][nt][1]),
                          "+f"(acc[mt][nt][2]), "+f"(acc[mt][nt][3])
                        : "r"(a[mt][0]), "r"(a[mt][1]), "r"(a[mt][2]), "r"(a[mt][3]),
                          "r"(b[nt][0]), "r"(b[nt][1]));
                }
        }
        __syncthreads();
    }

    #pragma unroll
    for (int mt = 0; mt < MT; mt++) {
        int r_lo = m0 + wm * 32 + mt * 16 + (lane >> 2);
        int r_hi = r_lo + 8;
        #pragma unroll
        for (int nt = 0; nt < NTc; nt++) {
            int c0 = n0 + wn * 64 + nt * 8 + 2 * (lane & 3);
            float v00 = acc[mt][nt][0], v01 = acc[mt][nt][1];
            float v10 = acc[mt][nt][2], v11 = acc[mt][nt][3];
            if (MODE == 5) {
                if (c0 < HSZ) {
                    __nv_bfloat16* ub = (__nv_bfloat16*)Cv;
                    *(__nv_bfloat162*)&ub[(size_t)r_lo * HSZ + c0] = __floats2bfloat162_rn(v00, v01);
                    *(__nv_bfloat162*)&ub[(size_t)r_hi * HSZ + c0] = __floats2bfloat162_rn(v10, v11);
                } else {
                    int e = c0 - HSZ;
                    float* fh = (float*)aux;
                    fh[(size_t)r_lo * ESZ + e] = v00;
                    fh[(size_t)r_lo * ESZ + e + 1] = v01;
                    fh[(size_t)r_hi * ESZ + e] = v10;
                    fh[(size_t)r_hi * ESZ + e + 1] = v11;
                }
            }
            if (MODE == 6) {
                float* Cf = (float*)Cv;
                float bb0 = b1[c0], bb1 = b1[c0 + 1];
                Cf[(size_t)r_lo * N + c0] = tanhf(v00 + aux[(size_t)r_lo * ESZ + c0] + bb0);
                Cf[(size_t)r_lo * N + c0 + 1] = tanhf(v01 + aux[(size_t)r_lo * ESZ + c0 + 1] + bb1);
                Cf[(size_t)r_hi * N + c0] = tanhf(v10 + aux[(size_t)r_hi * ESZ + c0] + bb0);
                Cf[(size_t)r_hi * N + c0 + 1] = tanhf(v11 + aux[(size_t)r_hi * ESZ + c0 + 1] + bb1);
            }
        }
    }
}

// ---------------- batched attention over all 32 timesteps (ctx only) ----------------
__global__ __launch_bounds__(256) void attn_all_kernel() {
    __shared__ __nv_bfloat16 hs_s[LLEN * HSZ];
    __shared__ float u_s[HSZ];
    __shared__ float sc[LLEN];
    __shared__ float mask_s[LLEN];

    const int r = blockIdx.x;
    const int j = r / BSZ;
    const int tid = threadIdx.x;
    const int warp = tid >> 5, lane = tid & 31;

    #pragma unroll
    for (int idx = tid; idx < LLEN * HSZ / 8; idx += 256) {
        int l = idx >> 6;
        int c8 = (idx & 63) * 8;
        uint4 v = *(const uint4*)&g_Hs[((size_t)l * NB + r) * HSZ + c8];
        *(uint4*)&hs_s[l * HSZ + c8] = v;
    }
    if (tid < LLEN) mask_s[tid] = g_mask[(j * LLEN + tid) * BSZ + (r % BSZ)];
    __syncthreads();

    for (int t = 0; t < TLEN; t++) {
        const size_t row = (size_t)t * NB + r;
        for (int k = tid; k < HSZ; k += 256)
            u_s[k] = __bfloat162float(g_ubf[row * HSZ + k]);
        __syncthreads();

        for (int l = warp; l < LLEN; l += 8) {
            float s = 0.f;
            for (int k = lane; k < HSZ; k += 32)
                s += __bfloat162float(hs_s[l * HSZ + k]) * u_s[k];
            #pragma unroll
            for (int off = 16; off > 0; off >>= 1) s += __shfl_down_sync(0xffffffffu, s, off);
            if (lane == 0) sc[l] = s + mask_s[l];
        }
        __syncthreads();

        if (warp == 0) {
            float v = sc[lane];
            float mx = v;
            #pragma unroll
            for (int off = 16; off > 0; off >>= 1) mx = fmaxf(mx, __shfl_xor_sync(0xffffffffu, mx, off));
            float e = expf(v - mx);
            float ssum = e;
            #pragma unroll
            for (int off = 16; off > 0; off >>= 1) ssum += __shfl_xor_sync(0xffffffffu, ssum, off);
            sc[lane] = e / ssum;
        }
        __syncthreads();

        __nv_bfloat16* cx_out = g_ctx + row * HSZ;
        #pragma unroll
        for (int kq = 0; kq < 2; kq++) {
            int k = tid + kq * 256;
            float cx = 0.f;
            #pragma unroll
            for (int l = 0; l < LLEN; l++) cx += sc[l] * __bfloat162float(hs_s[l * HSZ + k]);
            cx_out[k] = __float2bfloat16_rn(cx);
        }
        __syncthreads();
    }
}

// ---------------- pool + logits + log-softmax + score over all t ----------------
__global__ __launch_bounds__(256) void pool_score_all_kernel(
    const float* __restrict__ Vw, const float* __restrict__ Vb,
    const int* __restrict__ target, float* __restrict__ out) {
    extern __shared__ float dsm[];
    float* Vw_s = dsm;
    float* m_s  = dsm + ESZ * 132;
    float* lgs  = m_s + ESZ;
    __shared__ float red[2];

    const int b = blockIdx.x;
    const int tid = threadIdx.x;
    const int lane = tid & 31;

    for (int idx = tid; idx < V1SZ * ESZ; idx += 256) {
        int v = idx >> 7, e = idx & 127;
        Vw_s[e * 132 + v] = Vw[(size_t)v * ESZ + e];
    }
    __syncthreads();

    float score = 0.f, act = 1.f;
    for (int t = 0; t < TLEN; t++) {
        if (tid < ESZ) {
            const size_t base = ((size_t)t * NB + b) * ESZ + tid;
            float m = g_fc[base];
            #pragma unroll
            for (int jj = 1; jj < NEXN; jj++)
                m = fmaxf(m, g_fc[base + (size_t)jj * BSZ * ESZ]);
            m_s[tid] = m;
        }
        __syncthreads();

        if (tid < V1SZ) {
            float s = Vb[tid];
            #pragma unroll 8
            for (int e = 0; e < ESZ; e++) s += m_s[e] * Vw_s[e * 132 + tid];
            lgs[tid] = s;
        }
        __syncthreads();

        if (tid < 32) {
            float mx = -1e30f;
            for (int v = lane; v < V1SZ; v += 32) mx = fmaxf(mx, lgs[v]);
            #pragma unroll
            for (int off = 16; off > 0; off >>= 1) mx = fmaxf(mx, __shfl_xor_sync(0xffffffffu, mx, off));
            float ssum = 0.f;
            for (int v = lane; v < V1SZ; v += 32) ssum += expf(lgs[v] - mx);
            #pragma unroll
            for (int off = 16; off > 0; off >>= 1) ssum += __shfl_xor_sync(0xffffffffu, ssum, off);
            if (lane == 0) { red[0] = mx; red[1] = ssum; }
        }
        __syncthreads();

        int tg = target[t * BSZ + b];
        float ls = lgs[tg] - red[0] - logf(red[1]);
        score += ls * act;
        act *= (tg != VSZ) ? 1.f : 0.f;
        __syncthreads();
    }
    if (tid == 0) out[b] = score;
}

// ---------------- host orchestration ----------------
extern "C" void kernel_launch(void* const* d_in, const int* in_sizes, int n_in,
                              void* d_out, int out_size) {
    const int*   inputs  = (const int*)  d_in[0];
    const int*   target  = (const int*)  d_in[1];
    const float* enc_Wih = (const float*)d_in[2];
    const float* enc_Whh = (const float*)d_in[3];
    const float* enc_bih = (const float*)d_in[4];
    const float* enc_bhh = (const float*)d_in[5];
    const float* enc_h0  = (const float*)d_in[6];
    const float* enc_c0  = (const float*)d_in[7];
    const float* dec_Wih = (const float*)d_in[8];
    const float* dec_Whh = (const float*)d_in[9];
    const float* dec_bih = (const float*)d_in[10];
    const float* dec_bhh = (const float*)d_in[11];
    const float* dec_c0  = (const float*)d_in[12];
    const float* W_w     = (const float*)d_in[13];
    const float* W_b     = (const float*)d_in[14];
    const float* V_w     = (const float*)d_in[15];
    const float* V_b     = (const float*)d_in[16];
    const float* A_w     = (const float*)d_in[17];
    float* out = (float*)d_out;

    __nv_bfloat16 *WhhPE_p, *WhhPD_p, *Bu_p, *Ww2b_p, *Hd_p, *ubf_p, *ctx_p;
    float *fch_p, *fc_p;
    cudaGetSymbolAddress((void**)&WhhPE_p, g_WhhPE);
    cudaGetSymbolAddress((void**)&WhhPD_p, g_WhhPD);
    cudaGetSymbolAddress((void**)&Bu_p, g_Bu);
    cudaGetSymbolAddress((void**)&Ww2b_p, g_Ww2b);
    cudaGetSymbolAddress((void**)&Hd_p, g_Hd);
    cudaGetSymbolAddress((void**)&ubf_p, g_ubf);
    cudaGetSymbolAddress((void**)&ctx_p, g_ctx);
    cudaGetSymbolAddress((void**)&fch_p, g_fch);
    cudaGetSymbolAddress((void**)&fc_p, g_fc);

    const int ps_smem = (ESZ * 132 + ESZ + 132) * (int)sizeof(float);
    cudaFuncSetAttribute(pool_score_all_kernel, cudaFuncAttributeMaxDynamicSharedMemorySize, ps_smem);
    const int chain_smem = 3 * (256 + 128) * 40 * 2 + 32 * 256 * 4;   // 124928 B
    cudaFuncSetAttribute(chain_kernel, cudaFuncAttributeMaxDynamicSharedMemorySize, chain_smem);

    // ---- prep ----
    permute_whh_kernel<<<H4SZ, 256>>>(enc_Whh, WhhPE_p);
    permute_whh_kernel<<<H4SZ, 256>>>(dec_Whh, WhhPD_p);
    transpose_wih_both_kernel<<<dim3(V1SZ, 2), 256>>>(enc_Wih, enc_bih, enc_bhh,
                                                      dec_Wih, dec_bih, dec_bhh);
    build_tail_weights_kernel<<<(NU * HSZ + 255) / 256, 256>>>(A_w, W_w);
    init_all_kernel<<<(NB * HSZ + 255) / 256, 256>>>(enc_h0, inputs);

    // ---- persistent LSTM chain ----
    chain_kernel<<<dim3(H4SZ / 128, NB / 256), 512, chain_smem>>>(
        inputs, target, enc_c0, dec_c0);

    // ---- batched decoder tail ----
    // combined: [u | fch] = Hd @ [A_w ; Ww1]^T
    bf16_gemm_kernel<5><<<dim3(NU / 128, NT_ALL / 128), 256>>>(
        Hd_p, Bu_p, (void*)ubf_p, NT_ALL, NU, HSZ, nullptr, fch_p);
    attn_all_kernel<<<NB, 256>>>();
    // fc = tanh(ctx @ Ww2^T + fch + W_b)
    bf16_gemm_kernel<6><<<dim3(ESZ / 128, NT_ALL / 128), 256>>>(
        ctx_p, Ww2b_p, (void*)fc_p, NT_ALL, ESZ, HSZ, W_b, fch_p);
    pool_score_all_kernel<<<BSZ, 256, ps_smem>>>(V_w, V_b, target, out);
}

// round 17
// speedup vs baseline: 1.2183x; 1.2007x over previous
#include <cuda_runtime.h>
#include <cuda_bf16.h>
#include <math.h>
#include <stdint.h>

// ---------------- problem constants ----------------
#define VSZ   128
#define V1SZ  129
#define HSZ   512
#define H4SZ  2048
#define ESZ   128
#define NEXN  4
#define LLEN  32
#define BSZ   512
#define TLEN  32
#define NB    (NEXN * BSZ)      // 2048
#define NT_ALL (TLEN * NB)      // 65536
#define NEGV  (-1e9f)
#define NBH   ((size_t)NB * HSZ)
#define NU    (HSZ + ESZ)       // 640 stacked B rows for combined GEMM

// ---------------- device scratch (allocation-free) ----------------
__device__ __nv_bfloat16 g_Hs[(size_t)LLEN * NB * HSZ];     // bf16 hiddens (tail use)
__device__ __nv_bfloat16 g_Hd[(size_t)TLEN * NB * HSZ];
__device__ int8_t g_HsQ[(size_t)LLEN * NB * HSZ];           // int8 hiddens (chain A)
__device__ int8_t g_HdQ[(size_t)TLEN * NB * HSZ];
__device__ int8_t g_h0q[NB * HSZ];
__device__ __nv_bfloat16 g_ubf[(size_t)NT_ALL * HSZ];
__device__ float g_fch[(size_t)NT_ALL * ESZ];
__device__ __nv_bfloat16 g_ctx[(size_t)NT_ALL * HSZ];
__device__ float g_fc[(size_t)NT_ALL * ESZ];
__device__ float g_mask[NEXN * LLEN * BSZ];
__device__ int   g_idx[NB];
__device__ unsigned int g_bar;
__device__ int8_t g_WhhQE[H4SZ * HSZ];                      // int8 gate-interleaved Whh
__device__ int8_t g_WhhQD[H4SZ * HSZ];
__device__ float g_swE[H4SZ];                               // combined scale s_w/127
__device__ float g_swD[H4SZ];
__device__ float g_WihTE[V1SZ * H4SZ];
__device__ float g_WihTD[V1SZ * H4SZ];
__device__ __nv_bfloat16 g_Bu[NU * HSZ];
__device__ __nv_bfloat16 g_Ww2b[ESZ * HSZ];

__device__ __forceinline__ float sigmoidf_(float x) { return 1.f / (1.f + expf(-x)); }

// ---------------- ptx helpers ----------------
__device__ __forceinline__ void cp_async16(uint32_t dst, const void* src) {
    asm volatile("cp.async.cg.shared.global [%0], [%1], 16;\n" :: "r"(dst), "l"(src));
}
__device__ __forceinline__ void cp_commit() { asm volatile("cp.async.commit_group;\n"); }
template<int N> __device__ __forceinline__ void cp_wait() {
    asm volatile("cp.async.wait_group %0;\n" :: "n"(N));
}
__device__ __forceinline__ void ldm_x4(uint32_t& r0, uint32_t& r1, uint32_t& r2, uint32_t& r3,
                                       uint32_t addr) {
    asm volatile("ldmatrix.sync.aligned.m8n8.x4.shared.b16 {%0,%1,%2,%3}, [%4];"
                 : "=r"(r0), "=r"(r1), "=r"(r2), "=r"(r3) : "r"(addr));
}

// ---------------- prep kernels ----------------
// int8 quantize Whh, gate-interleaved; per-row scale (incl /127 for h)
__global__ void quant_whh_kernel(const float* __restrict__ Whh,
                                 int8_t* __restrict__ WhhQ, float* __restrict__ sw) {
    __shared__ float red[256];
    int np = blockIdx.x;
    int h = np >> 2, g = np & 3;
    int orig = g * HSZ + h;
    float mx = 0.f;
    for (int k = threadIdx.x; k < HSZ; k += 256)
        mx = fmaxf(mx, fabsf(Whh[(size_t)orig * HSZ + k]));
    red[threadIdx.x] = mx;
    __syncthreads();
    for (int s = 128; s > 0; s >>= 1) {
        if (threadIdx.x < s) red[threadIdx.x] = fmaxf(red[threadIdx.x], red[threadIdx.x + s]);
        __syncthreads();
    }
    float s_w = red[0] / 127.f;
    float inv = (s_w > 0.f) ? 1.f / s_w : 0.f;
    for (int k = threadIdx.x; k < HSZ; k += 256) {
        int q = __float2int_rn(Whh[(size_t)orig * HSZ + k] * inv);
        q = max(-127, min(127, q));
        WhhQ[np * HSZ + k] = (int8_t)q;
    }
    if (threadIdx.x == 0) sw[np] = s_w / 127.f;   // combined: × (1/127) for h scale
}

__global__ void transpose_wih_both_kernel(
    const float* __restrict__ WihE, const float* __restrict__ bihE, const float* __restrict__ bhhE,
    const float* __restrict__ WihD, const float* __restrict__ bihD, const float* __restrict__ bhhD) {
    int v = blockIdx.x;
    const float* Wih = blockIdx.y ? WihD : WihE;
    const float* bih = blockIdx.y ? bihD : bihE;
    const float* bhh = blockIdx.y ? bhhD : bhhE;
    float* WihT = blockIdx.y ? g_WihTD : g_WihTE;
    for (int np = threadIdx.x; np < H4SZ; np += 256) {
        int h = np >> 2, g = np & 3;
        int orig = g * HSZ + h;
        WihT[(size_t)v * H4SZ + np] = Wih[(size_t)orig * V1SZ + v] + bih[orig] + bhh[orig];
    }
}

__global__ void build_tail_weights_kernel(const float* __restrict__ Aw,
                                          const float* __restrict__ Ww) {
    int i = blockIdx.x * blockDim.x + threadIdx.x;
    if (i < NU * HSZ) {
        int row = i / HSZ, k = i % HSZ;
        float v = (row < HSZ) ? Aw[(size_t)row * HSZ + k]
                              : Ww[(size_t)(row - HSZ) * (2 * HSZ) + k];
        g_Bu[i] = __float2bfloat16_rn(v);
    }
    if (i < ESZ * HSZ) {
        int e = i / HSZ, k = i % HSZ;
        g_Ww2b[i] = __float2bfloat16_rn(Ww[(size_t)e * (2 * HSZ) + HSZ + k]);
    }
}

__global__ void init_all_kernel(const float* __restrict__ h0, const int* __restrict__ inputs) {
    int idx = blockIdx.x * blockDim.x + threadIdx.x;
    if (idx == 0) g_bar = 0u;
    if (idx < NB * HSZ) {
        int q = __float2int_rn(h0[idx & (HSZ - 1)] * 127.f);
        g_h0q[idx] = (int8_t)max(-127, min(127, q));
    }
    if (idx < NB) {
        int r = idx;
        int j = r / BSZ, b = r % BSZ;
        float a = 1.f;
        int cnt = 0;
        #pragma unroll
        for (int l = 0; l < LLEN; l++) {
            g_mask[(j * LLEN + l) * BSZ + b] = (a > 0.f) ? 0.f : NEGV;
            cnt += (a > 0.f) ? 1 : 0;
            a *= (inputs[(j * LLEN + l) * BSZ + b] != VSZ) ? 1.f : 0.f;
        }
        g_idx[r] = cnt - 1;
    }
}

// ================= persistent INT8-IMMA LSTM chain =================
// 128 CTAs (16 n-tiles x 8 m-tiles), CTA 256x128, 512 threads (16 warps 8x2,
// warp tile 32x64). K=512 s8 in 8 iters of 64 s8; per iter 2x m16n8k32 IMMA.
// Byte layout identical to the bf16 version (s8 pair == bf16 slot).
__global__ __launch_bounds__(512, 1)
void chain_kernel(const int* __restrict__ inputs, const int* __restrict__ target,
                  const float* __restrict__ enc_c0, const float* __restrict__ dec_c0) {
    constexpr int BM = 256, BN = 128;
    constexpr int KB = HSZ;                       // 512 bytes per row (s8)
    constexpr int BKB = 64;                       // bytes per k-iter
    constexpr int AST = 40;                       // "b16-unit" stride = 80 B rows
    constexpr int MT = 2, NTc = 8;
    constexpr int STAGE = (BM + BN) * AST;        // b16 units per stage (same as bf16 ver)
    constexpr int NSTAGE = 3;
    constexpr int NIT = KB / BKB;                 // 8
    constexpr int NCTA = 128;

    extern __shared__ __nv_bfloat16 smd[];
    float* c_s = (float*)(smd + NSTAGE * STAGE);
    const uint32_t smbase = (uint32_t)__cvta_generic_to_shared(smd);

    const int tid = threadIdx.x;
    const int warp = tid >> 5, lane = tid & 31;
    const int wm = warp >> 1;
    const int wn = warp & 1;
    const int m0 = blockIdx.y * BM, n0 = blockIdx.x * BN;
    const unsigned FULL = 0xffffffffu;

    __shared__ float s_sw[BN];
    for (int i = tid; i < 32 * 256; i += 512)
        c_s[i] = enc_c0[blockIdx.x * 32 + (i >> 8)];
    if (tid < BN) s_sw[tid] = g_swE[n0 + tid];
    __syncthreads();

    for (int t = 0; t < LLEN + TLEN; t++) {
        const bool enc = t < LLEN;
        const int8_t* Bw = enc ? g_WhhQE : g_WhhQD;
        const float* WihT = enc ? g_WihTE : g_WihTD;
        const int8_t* A;
        int gather = 0;
        if (t == 0)            A = g_h0q;
        else if (t < LLEN)     A = g_HsQ + (size_t)(t - 1) * NBH;
        else if (t == LLEN)  { A = g_HsQ; gather = 1; }
        else                   A = g_HdQ + (size_t)(t - LLEN - 1) * NBH;
        __nv_bfloat16* Hout = enc ? (g_Hs + (size_t)t * NBH)
                                  : (g_Hd + (size_t)(t - LLEN) * NBH);
        int8_t* HoutQ = enc ? (g_HsQ + (size_t)t * NBH)
                            : (g_HdQ + (size_t)(t - LLEN) * NBH);
        int tokmode; const int* tokp = nullptr;
        if (t < LLEN)      { tokmode = 1; tokp = inputs + t * BSZ; }
        else if (t == LLEN)  tokmode = 0;
        else               { tokmode = 2; tokp = target + (t - LLEN - 1) * BSZ; }

        if (t == LLEN) {
            for (int i = tid; i < 32 * 256; i += 512)
                c_s[i] = dec_c0[blockIdx.x * 32 + (i >> 8)];
            if (tid < BN) s_sw[tid] = g_swD[n0 + tid];
            __syncthreads();
        }

        int acc[MT][NTc][4];
        #pragma unroll
        for (int mt = 0; mt < MT; mt++)
            #pragma unroll
            for (int nt = 0; nt < NTc; nt++)
                #pragma unroll
                for (int q = 0; q < 4; q++) acc[mt][nt][q] = 0;

        auto load_stage = [&](int it) {
            const int k0b = it * BKB;
            const uint32_t base = smbase + (uint32_t)(it % NSTAGE) * STAGE * 2;
            #pragma unroll
            for (int ii = 0; ii < (BM + BN) * 4 / 512; ii++) {
                int c = tid + ii * 512;
                bool isB = c >= BM * 4;
                int cc = isB ? c - BM * 4 : c;
                int row = cc >> 2, part = cc & 3;
                const int8_t* src;
                if (isB) {
                    src = Bw + (size_t)(n0 + row) * KB + k0b + part * 16;
                } else if (gather) {
                    int rg2 = m0 + row;
                    src = g_HsQ + ((size_t)g_idx[rg2] * NB + rg2) * HSZ + k0b + part * 16;
                } else {
                    src = A + (size_t)(m0 + row) * KB + k0b + part * 16;
                }
                uint32_t dst = base + (uint32_t)(((isB ? BM + row : row) * AST + part * 8) * 2);
                cp_async16(dst, src);
            }
            cp_commit();
        };

        load_stage(0);
        load_stage(1);

        for (int it = 0; it < NIT; it++) {
            if (it == NIT - 1) cp_wait<0>(); else cp_wait<1>();
            __syncthreads();
            if (it + 2 < NIT) load_stage(it + 2);

            const uint32_t aBase = smbase + (uint32_t)(it % NSTAGE) * STAGE * 2;
            const uint32_t bBase = aBase + BM * AST * 2;

            #pragma unroll
            for (int kk = 0; kk < 2; kk++) {
                uint32_t a[MT][4];
                #pragma unroll
                for (int mt = 0; mt < MT; mt++) {
                    int row = wm * 32 + mt * 16 + (lane & 15);
                    int col = kk * 16 + (lane >> 4) * 8;
                    ldm_x4(a[mt][0], a[mt][1], a[mt][2], a[mt][3],
                           aBase + (uint32_t)((row * AST + col) * 2));
                }
                uint32_t b[NTc][2];
                #pragma unroll
                for (int ntp = 0; ntp < NTc / 2; ntp++) {
                    int row = wn * 64 + ntp * 16 + ((lane >> 4) << 3) + (lane & 7);
                    int col = kk * 16 + ((lane >> 3) & 1) * 8;
                    ldm_x4(b[2 * ntp][0], b[2 * ntp][1], b[2 * ntp + 1][0], b[2 * ntp + 1][1],
                           bBase + (uint32_t)((row * AST + col) * 2));
                }
                #pragma unroll
                for (int mt = 0; mt < MT; mt++)
                    #pragma unroll
                    for (int nt = 0; nt < NTc; nt++) {
                        asm volatile(
                            "mma.sync.aligned.m16n8k32.row.col.s32.s8.s8.s32 "
                            "{%0,%1,%2,%3}, {%4,%5,%6,%7}, {%8,%9}, {%0,%1,%2,%3};"
                            : "+r"(acc[mt][nt][0]), "+r"(acc[mt][nt][1]),
                              "+r"(acc[mt][nt][2]), "+r"(acc[mt][nt][3])
                            : "r"(a[mt][0]), "r"(a[mt][1]), "r"(a[mt][2]), "r"(a[mt][3]),
                              "r"(b[nt][0]), "r"(b[nt][1]));
                    }
            }
        }
        __syncthreads();

        // -------- fused LSTM epilogue --------
        #pragma unroll
        for (int mt = 0; mt < MT; mt++) {
            int rl_lo = wm * 32 + mt * 16 + (lane >> 2);
            int rl_hi = rl_lo + 8;
            int r_lo = m0 + rl_lo, r_hi = m0 + rl_hi;
            int tok_lo = VSZ, tok_hi = VSZ;
            if (tokmode == 1) {
                tok_lo = tokp[(r_lo / BSZ) * (LLEN * BSZ) + (r_lo % BSZ)];
                tok_hi = tokp[(r_hi / BSZ) * (LLEN * BSZ) + (r_hi % BSZ)];
            } else if (tokmode == 2) {
                tok_lo = tokp[r_lo % BSZ];
                tok_hi = tokp[r_hi % BSZ];
            }
            const float* wl = WihT + (size_t)tok_lo * H4SZ;
            const float* wh_ = WihT + (size_t)tok_hi * H4SZ;
            #pragma unroll
            for (int nt = 0; nt < NTc; nt++) {
                int cl = wn * 64 + nt * 8 + 2 * (lane & 3);   // local col
                int c0 = n0 + cl;
                float sw0 = s_sw[cl], sw1 = s_sw[cl + 1];
                float2 el = *(const float2*)&wl[c0];
                float2 eh = *(const float2*)&wh_[c0];
                float v00 = (float)acc[mt][nt][0] * sw0 + el.x;
                float v01 = (float)acc[mt][nt][1] * sw1 + el.y;
                float v10 = (float)acc[mt][nt][2] * sw0 + eh.x;
                float v11 = (float)acc[mt][nt][3] * sw1 + eh.y;
                float p00 = __shfl_xor_sync(FULL, v00, 1);
                float p01 = __shfl_xor_sync(FULL, v01, 1);
                float p10 = __shfl_xor_sync(FULL, v10, 1);
                float p11 = __shfl_xor_sync(FULL, v11, 1);
                if ((lane & 1) == 0) {
                    int hl = wn * 16 + nt * 2 + ((lane & 3) >> 1);
                    int hg = blockIdx.x * 32 + hl;
                    {
                        float cold = c_s[hl * 256 + rl_lo];
                        float c2 = sigmoidf_(v01) * cold + sigmoidf_(v00) * tanhf(p00);
                        float h2 = sigmoidf_(p01) * tanhf(c2);
                        c_s[hl * 256 + rl_lo] = c2;
                        Hout[(size_t)r_lo * HSZ + hg] = __float2bfloat16_rn(h2);
                        int q = __float2int_rn(h2 * 127.f);
                        HoutQ[(size_t)r_lo * HSZ + hg] = (int8_t)max(-127, min(127, q));
                    }
                    {
                        float cold = c_s[hl * 256 + rl_hi];
                        float c2 = sigmoidf_(v11) * cold + sigmoidf_(v10) * tanhf(p10);
                        float h2 = sigmoidf_(p11) * tanhf(c2);
                        c_s[hl * 256 + rl_hi] = c2;
                        Hout[(size_t)r_hi * HSZ + hg] = __float2bfloat16_rn(h2);
                        int q = __float2int_rn(h2 * 127.f);
                        HoutQ[(size_t)r_hi * HSZ + hg] = (int8_t)max(-127, min(127, q));
                    }
                }
            }
        }

        // -------- grid barrier --------
        __threadfence();
        __syncthreads();
        if (tid == 0) {
            atomicAdd(&g_bar, 1u);
            unsigned need = (unsigned)NCTA * (unsigned)(t + 1);
            while (*(volatile unsigned*)&g_bar < need) { }
        }
        __syncthreads();
        __threadfence();
    }
}

// ================= generic bf16 GEMM (batched tail) =================
// MODE 5: combined u+fch store; MODE 6: fc = tanh(acc + fch + b1)
template<int MODE>
__global__ __launch_bounds__(256)
void bf16_gemm_kernel(const __nv_bfloat16* __restrict__ A, const __nv_bfloat16* __restrict__ Bw,
                      void* __restrict__ Cv, int M, int N, int K,
                      const float* __restrict__ b1, const float* __restrict__ aux) {
    constexpr int BM = 128, BN = 128, BK = 32;
    constexpr int AST = 40;
    constexpr int MT = 2, NTc = 8;
    constexpr int STAGE = (BM + BN) * AST;

    __shared__ __nv_bfloat16 sm[2 * STAGE];
    const uint32_t smbase = (uint32_t)__cvta_generic_to_shared(sm);

    const int tid = threadIdx.x;
    const int warp = tid >> 5, lane = tid & 31;
    const int wm = warp >> 1;
    const int wn = warp & 1;
    const int m0 = blockIdx.y * BM, n0 = blockIdx.x * BN;
    const int NIT = K / BK;

    float acc[MT][NTc][4];
    #pragma unroll
    for (int mt = 0; mt < MT; mt++)
        #pragma unroll
        for (int nt = 0; nt < NTc; nt++)
            #pragma unroll
            for (int q = 0; q < 4; q++) acc[mt][nt][q] = 0.f;

    auto load_stage = [&](int it, int buf) {
        const int k0 = it * BK;
        const uint32_t base = smbase + (uint32_t)buf * STAGE * 2;
        #pragma unroll
        for (int c = tid; c < (BM + BN) * 4; c += 256) {
            bool isB = c >= BM * 4;
            int cc = isB ? c - BM * 4 : c;
            int row = cc >> 2, part = cc & 3;
            const __nv_bfloat16* src = isB
                ? (Bw + (size_t)(n0 + row) * K + k0 + part * 8)
                : (A  + (size_t)(m0 + row) * K + k0 + part * 8);
            uint32_t dst = base + (uint32_t)(((isB ? BM + row : row) * AST + part * 8) * 2);
            cp_async16(dst, src);
        }
    };

    load_stage(0, 0);
    cp_commit();

    for (int it = 0; it < NIT; it++) {
        if (it + 1 < NIT) { load_stage(it + 1, (it + 1) & 1); cp_commit(); cp_wait<1>(); }
        else              { cp_wait<0>(); }
        __syncthreads();

        const uint32_t aBase = smbase + (uint32_t)(it & 1) * STAGE * 2;
        const uint32_t bBase = aBase + BM * AST * 2;

        #pragma unroll
        for (int kk = 0; kk < 2; kk++) {
            uint32_t a[MT][4];
            #pragma unroll
            for (int mt = 0; mt < MT; mt++) {
                int row = wm * 32 + mt * 16 + (lane & 15);
                int col = kk * 16 + (lane >> 4) * 8;
                ldm_x4(a[mt][0], a[mt][1], a[mt][2], a[mt][3],
                       aBase + (uint32_t)((row * AST + col) * 2));
            }
            uint32_t b[NTc][2];
            #pragma unroll
            for (int ntp = 0; ntp < NTc / 2; ntp++) {
                int row = wn * 64 + ntp * 16 + ((lane >> 4) << 3) + (lane & 7);
                int col = kk * 16 + ((lane >> 3) & 1) * 8;
                ldm_x4(b[2 * ntp][0], b[2 * ntp][1], b[2 * ntp + 1][0], b[2 * ntp + 1][1],
                       bBase + (uint32_t)((row * AST + col) * 2));
            }
            #pragma unroll
            for (int mt = 0; mt < MT; mt++)
                #pragma unroll
                for (int nt = 0; nt < NTc; nt++) {
                    asm volatile(
                        "mma.sync.aligned.m16n8k16.row.col.f32.bf16.bf16.f32 "
                        "{%0,%1,%2,%3}, {%4,%5,%6,%7}, {%8,%9}, {%0,%1,%2,%3};"
                        : "+f"(acc[mt][nt][0]), "+f"(acc[mt][nt][1]),
                          "+f"(acc[mt][nt][2]), "+f"(acc[mt][nt][3])
                        : "r"(a[mt][0]), "r"(a[mt][1]), "r"(a[mt][2]), "r"(a[mt][3]),
                          "r"(b[nt][0]), "r"(b[nt][1]));
                }
        }
        __syncthreads();
    }

    #pragma unroll
    for (int mt = 0; mt < MT; mt++) {
        int r_lo = m0 + wm * 32 + mt * 16 + (lane >> 2);
        int r_hi = r_lo + 8;
        #pragma unroll
        for (int nt = 0; nt < NTc; nt++) {
            int c0 = n0 + wn * 64 + nt * 8 + 2 * (lane & 3);
            float v00 = acc[mt][nt][0], v01 = acc[mt][nt][1];
            float v10 = acc[mt][nt][2], v11 = acc[mt][nt][3];
            if (MODE == 5) {
                if (c0 < HSZ) {
                    __nv_bfloat16* ub = (__nv_bfloat16*)Cv;
                    *(__nv_bfloat162*)&ub[(size_t)r_lo * HSZ + c0] = __floats2bfloat162_rn(v00, v01);
                    *(__nv_bfloat162*)&ub[(size_t)r_hi * HSZ + c0] = __floats2bfloat162_rn(v10, v11);
                } else {
                    int e = c0 - HSZ;
                    float* fh = (float*)aux;
                    fh[(size_t)r_lo * ESZ + e] = v00;
                    fh[(size_t)r_lo * ESZ + e + 1] = v01;
                    fh[(size_t)r_hi * ESZ + e] = v10;
                    fh[(size_t)r_hi * ESZ + e + 1] = v11;
                }
            }
            if (MODE == 6) {
                float* Cf = (float*)Cv;
                float bb0 = b1[c0], bb1 = b1[c0 + 1];
                Cf[(size_t)r_lo * N + c0] = tanhf(v00 + aux[(size_t)r_lo * ESZ + c0] + bb0);
                Cf[(size_t)r_lo * N + c0 + 1] = tanhf(v01 + aux[(size_t)r_lo * ESZ + c0 + 1] + bb1);
                Cf[(size_t)r_hi * N + c0] = tanhf(v10 + aux[(size_t)r_hi * ESZ + c0] + bb0);
                Cf[(size_t)r_hi * N + c0 + 1] = tanhf(v11 + aux[(size_t)r_hi * ESZ + c0 + 1] + bb1);
            }
        }
    }
}

// ---------------- batched attention over all 32 timesteps (ctx only) ----------------
__global__ __launch_bounds__(256) void attn_all_kernel() {
    __shared__ __nv_bfloat16 hs_s[LLEN * HSZ];
    __shared__ float u_s[HSZ];
    __shared__ float sc[LLEN];
    __shared__ float mask_s[LLEN];

    const int r = blockIdx.x;
    const int j = r / BSZ;
    const int tid = threadIdx.x;
    const int warp = tid >> 5, lane = tid & 31;

    #pragma unroll
    for (int idx = tid; idx < LLEN * HSZ / 8; idx += 256) {
        int l = idx >> 6;
        int c8 = (idx & 63) * 8;
        uint4 v = *(const uint4*)&g_Hs[((size_t)l * NB + r) * HSZ + c8];
        *(uint4*)&hs_s[l * HSZ + c8] = v;
    }
    if (tid < LLEN) mask_s[tid] = g_mask[(j * LLEN + tid) * BSZ + (r % BSZ)];
    __syncthreads();

    for (int t = 0; t < TLEN; t++) {
        const size_t row = (size_t)t * NB + r;
        for (int k = tid; k < HSZ; k += 256)
            u_s[k] = __bfloat162float(g_ubf[row * HSZ + k]);
        __syncthreads();

        for (int l = warp; l < LLEN; l += 8) {
            float s = 0.f;
            for (int k = lane; k < HSZ; k += 32)
                s += __bfloat162float(hs_s[l * HSZ + k]) * u_s[k];
            #pragma unroll
            for (int off = 16; off > 0; off >>= 1) s += __shfl_down_sync(0xffffffffu, s, off);
            if (lane == 0) sc[l] = s + mask_s[l];
        }
        __syncthreads();

        if (warp == 0) {
            float v = sc[lane];
            float mx = v;
            #pragma unroll
            for (int off = 16; off > 0; off >>= 1) mx = fmaxf(mx, __shfl_xor_sync(0xffffffffu, mx, off));
            float e = expf(v - mx);
            float ssum = e;
            #pragma unroll
            for (int off = 16; off > 0; off >>= 1) ssum += __shfl_xor_sync(0xffffffffu, ssum, off);
            sc[lane] = e / ssum;
        }
        __syncthreads();

        __nv_bfloat16* cx_out = g_ctx + row * HSZ;
        #pragma unroll
        for (int kq = 0; kq < 2; kq++) {
            int k = tid + kq * 256;
            float cx = 0.f;
            #pragma unroll
            for (int l = 0; l < LLEN; l++) cx += sc[l] * __bfloat162float(hs_s[l * HSZ + k]);
            cx_out[k] = __float2bfloat16_rn(cx);
        }
        __syncthreads();
    }
}

// ---------------- pool + logits + log-softmax + score over all t ----------------
__global__ __launch_bounds__(256) void pool_score_all_kernel(
    const float* __restrict__ Vw, const float* __restrict__ Vb,
    const int* __restrict__ target, float* __restrict__ out) {
    extern __shared__ float dsm[];
    float* Vw_s = dsm;
    float* m_s  = dsm + ESZ * 132;
    float* lgs  = m_s + ESZ;
    __shared__ float red[2];

    const int b = blockIdx.x;
    const int tid = threadIdx.x;
    const int lane = tid & 31;

    for (int idx = tid; idx < V1SZ * ESZ; idx += 256) {
        int v = idx >> 7, e = idx & 127;
        Vw_s[e * 132 + v] = Vw[(size_t)v * ESZ + e];
    }
    __syncthreads();

    float score = 0.f, act = 1.f;
    for (int t = 0; t < TLEN; t++) {
        if (tid < ESZ) {
            const size_t base = ((size_t)t * NB + b) * ESZ + tid;
            float m = g_fc[base];
            #pragma unroll
            for (int jj = 1; jj < NEXN; jj++)
                m = fmaxf(m, g_fc[base + (size_t)jj * BSZ * ESZ]);
            m_s[tid] = m;
        }
        __syncthreads();

        if (tid < V1SZ) {
            float s = Vb[tid];
            #pragma unroll 8
            for (int e = 0; e < ESZ; e++) s += m_s[e] * Vw_s[e * 132 + tid];
            lgs[tid] = s;
        }
        __syncthreads();

        if (tid < 32) {
            float mx = -1e30f;
            for (int v = lane; v < V1SZ; v += 32) mx = fmaxf(mx, lgs[v]);
            #pragma unroll
            for (int off = 16; off > 0; off >>= 1) mx = fmaxf(mx, __shfl_xor_sync(0xffffffffu, mx, off));
            float ssum = 0.f;
            for (int v = lane; v < V1SZ; v += 32) ssum += expf(lgs[v] - mx);
            #pragma unroll
            for (int off = 16; off > 0; off >>= 1) ssum += __shfl_xor_sync(0xffffffffu, ssum, off);
            if (lane == 0) { red[0] = mx; red[1] = ssum; }
        }
        __syncthreads();

        int tg = target[t * BSZ + b];
        float ls = lgs[tg] - red[0] - logf(red[1]);
        score += ls * act;
        act *= (tg != VSZ) ? 1.f : 0.f;
        __syncthreads();
    }
    if (tid == 0) out[b] = score;
}

// ---------------- host orchestration ----------------
extern "C" void kernel_launch(void* const* d_in, const int* in_sizes, int n_in,
                              void* d_out, int out_size) {
    const int*   inputs  = (const int*)  d_in[0];
    const int*   target  = (const int*)  d_in[1];
    const float* enc_Wih = (const float*)d_in[2];
    const float* enc_Whh = (const float*)d_in[3];
    const float* enc_bih = (const float*)d_in[4];
    const float* enc_bhh = (const float*)d_in[5];
    const float* enc_h0  = (const float*)d_in[6];
    const float* enc_c0  = (const float*)d_in[7];
    const float* dec_Wih = (const float*)d_in[8];
    const float* dec_Whh = (const float*)d_in[9];
    const float* dec_bih = (const float*)d_in[10];
    const float* dec_bhh = (const float*)d_in[11];
    const float* dec_c0  = (const float*)d_in[12];
    const float* W_w     = (const float*)d_in[13];
    const float* W_b     = (const float*)d_in[14];
    const float* V_w     = (const float*)d_in[15];
    const float* V_b     = (const float*)d_in[16];
    const float* A_w     = (const float*)d_in[17];
    float* out = (float*)d_out;

    int8_t *WhhQE_p, *WhhQD_p;
    float *swE_p, *swD_p, *fch_p, *fc_p;
    __nv_bfloat16 *Bu_p, *Ww2b_p, *Hd_p, *ubf_p, *ctx_p;
    cudaGetSymbolAddress((void**)&WhhQE_p, g_WhhQE);
    cudaGetSymbolAddress((void**)&WhhQD_p, g_WhhQD);
    cudaGetSymbolAddress((void**)&swE_p, g_swE);
    cudaGetSymbolAddress((void**)&swD_p, g_swD);
    cudaGetSymbolAddress((void**)&Bu_p, g_Bu);
    cudaGetSymbolAddress((void**)&Ww2b_p, g_Ww2b);
    cudaGetSymbolAddress((void**)&Hd_p, g_Hd);
    cudaGetSymbolAddress((void**)&ubf_p, g_ubf);
    cudaGetSymbolAddress((void**)&ctx_p, g_ctx);
    cudaGetSymbolAddress((void**)&fch_p, g_fch);
    cudaGetSymbolAddress((void**)&fc_p, g_fc);

    const int ps_smem = (ESZ * 132 + ESZ + 132) * (int)sizeof(float);
    cudaFuncSetAttribute(pool_score_all_kernel, cudaFuncAttributeMaxDynamicSharedMemorySize, ps_smem);
    const int chain_smem = 3 * (256 + 128) * 40 * 2 + 32 * 256 * 4;
    cudaFuncSetAttribute(chain_kernel, cudaFuncAttributeMaxDynamicSharedMemorySize, chain_smem);

    // ---- prep ----
    quant_whh_kernel<<<H4SZ, 256>>>(enc_Whh, WhhQE_p, swE_p);
    quant_whh_kernel<<<H4SZ, 256>>>(dec_Whh, WhhQD_p, swD_p);
    transpose_wih_both_kernel<<<dim3(V1SZ, 2), 256>>>(enc_Wih, enc_bih, enc_bhh,
                                                      dec_Wih, dec_bih, dec_bhh);
    build_tail_weights_kernel<<<(NU * HSZ + 255) / 256, 256>>>(A_w, W_w);
    init_all_kernel<<<(NB * HSZ + 255) / 256, 256>>>(enc_h0, inputs);

    // ---- persistent INT8 LSTM chain ----
    chain_kernel<<<dim3(H4SZ / 128, NB / 256), 512, chain_smem>>>(
        inputs, target, enc_c0, dec_c0);

    // ---- batched decoder tail ----
    bf16_gemm_kernel<5><<<dim3(NU / 128, NT_ALL / 128), 256>>>(
        Hd_p, Bu_p, (void*)ubf_p, NT_ALL, NU, HSZ, nullptr, fch_p);
    attn_all_kernel<<<NB, 256>>>();
    bf16_gemm_kernel<6><<<dim3(ESZ / 128, NT_ALL / 128), 256>>>(
        ctx_p, Ww2b_p, (void*)fc_p, NT_ALL, ESZ, HSZ, W_b, fch_p);
    pool_score_all_kernel<<<BSZ, 256, ps_smem>>>(V_w, V_b, target, out);
}